// round 10
// baseline (speedup 1.0000x reference)
#include <cuda_runtime.h>
#include <cuda_bf16.h>
#include <math.h>
#include <stdint.h>

#define C_DIM   1024
#define N_HEADS 16
#define HD      64
#define N_LAYERS 6
#define HID_DIM 4096
#define BATCH   2
#define SEQ     2048
#define NROWS   (BATCH*SEQ)
#define WIN     1000

// ================= scratch (no allocations allowed) =================
__device__ float g_x   [NROWS * C_DIM];
__device__ float g_tmp [NROWS * C_DIM];
__device__ __nv_bfloat16 g_xh[NROWS * C_DIM],  g_xl[NROWS * C_DIM];
__device__ __nv_bfloat16 g_ah[NROWS * C_DIM],  g_al[NROWS * C_DIM];
__device__ __nv_bfloat16 g_hh[NROWS * HID_DIM], g_hl[NROWS * HID_DIM];
__device__ __nv_bfloat16 g_qkvh[NROWS * 3 * C_DIM], g_qkvl[NROWS * 3 * C_DIM];
// per-layer split weight staging (reused; max 4M elems) + dedicated Wo staging
#define WMAX (HID_DIM * C_DIM)
__device__ __nv_bfloat16 g_wh[WMAX], g_wl[WMAX];
__device__ __nv_bfloat16 g_vh[C_DIM * C_DIM], g_vl[C_DIM * C_DIM];

// ================= helpers =================
__device__ __forceinline__ uint32_t smem_to_u32(const void* p) {
    uint32_t a;
    asm("{ .reg .u64 t; cvta.to.shared.u64 t, %1; cvt.u32.u64 %0, t; }" : "=r"(a) : "l"(p));
    return a;
}
#define SMEM_SWIZZLE_128B(x) ((x) ^ (((x) >> 3) & 0x70))

__device__ __forceinline__ void ldsm4(uint32_t* r, uint32_t addr) {
    asm volatile("ldmatrix.sync.aligned.m8n8.x4.shared.b16 {%0,%1,%2,%3}, [%4];"
                 : "=r"(r[0]), "=r"(r[1]), "=r"(r[2]), "=r"(r[3]) : "r"(addr));
}
__device__ __forceinline__ void ldsm4t(uint32_t* r, uint32_t addr) {
    asm volatile("ldmatrix.sync.aligned.m8n8.x4.trans.shared.b16 {%0,%1,%2,%3}, [%4];"
                 : "=r"(r[0]), "=r"(r[1]), "=r"(r[2]), "=r"(r[3]) : "r"(addr));
}
__device__ __forceinline__ void mma16816(float* d, const uint32_t* a, uint32_t b0, uint32_t b1) {
    asm volatile("mma.sync.aligned.m16n8k16.row.col.f32.bf16.bf16.f32 "
                 "{%0,%1,%2,%3}, {%4,%5,%6,%7}, {%8,%9}, {%0,%1,%2,%3};"
                 : "+f"(d[0]), "+f"(d[1]), "+f"(d[2]), "+f"(d[3])
                 : "r"(a[0]), "r"(a[1]), "r"(a[2]), "r"(a[3]), "r"(b0), "r"(b1));
}
__device__ __forceinline__ uint32_t packbf(float lo, float hi) {
    uint32_t r;
    asm("cvt.rn.bf16x2.f32 %0, %1, %2;" : "=r"(r) : "f"(hi), "f"(lo));
    return r;
}
__device__ __forceinline__ void split_pair(float v, __nv_bfloat16& hi, __nv_bfloat16& lo) {
    hi = __float2bfloat16(v);
    lo = __float2bfloat16(v - __bfloat162float(hi));
}
#define CPA16(dst, src) \
    asm volatile("cp.async.cg.shared.global [%0], [%1], 16;" :: "r"(dst), "l"(src))

// ================= weight split kernel =================
__global__ void split_f32_kernel(const float* __restrict__ w, __nv_bfloat16* __restrict__ h,
                                 __nv_bfloat16* __restrict__ l, int n) {
    int i = blockIdx.x * blockDim.x + threadIdx.x;
    int stride = gridDim.x * blockDim.x;
    for (; i < n; i += stride) {
        float v = w[i];
        __nv_bfloat16 hi, lo;
        split_pair(v, hi, lo);
        h[i] = hi; l[i] = lo;
    }
}

// ================= block reduce =================
__device__ __forceinline__ float blk_sum(float v, float* sh) {
    int tid = threadIdx.x;
    sh[tid] = v; __syncthreads();
#pragma unroll
    for (int s = 128; s > 0; s >>= 1) { if (tid < s) sh[tid] += sh[tid + s]; __syncthreads(); }
    float r = sh[0]; __syncthreads();
    return r;
}

// ================= input LN + positional embedding =================
__global__ __launch_bounds__(256) void embed_ln_kernel(
    const float* __restrict__ x, const float* __restrict__ g, const float* __restrict__ b,
    float* __restrict__ out, __nv_bfloat16* __restrict__ oh, __nv_bfloat16* __restrict__ ol)
{
    __shared__ float sh[256];
    int r = blockIdx.x, t = r % SEQ, tid = threadIdx.x;
    const float* xr = x + (size_t)r * C_DIM;
    float v[4]; float s = 0.f;
#pragma unroll
    for (int i = 0; i < 4; i++) { v[i] = xr[tid + 256 * i]; s += v[i]; }
    float mean = blk_sum(s, sh) * (1.0f / C_DIM);
    float d2 = 0.f;
#pragma unroll
    for (int i = 0; i < 4; i++) { float d = v[i] - mean; d2 += d * d; }
    float inv = rsqrtf(blk_sum(d2, sh) * (1.0f / C_DIM) + 1e-5f);
    const float kln = 9.2103403719761836f / 511.0f;
    float tf = (float)t;
#pragma unroll
    for (int i = 0; i < 4; i++) {
        int c = tid + 256 * i;
        float ph = (c < 512) ? tf * expf(-((float)c) * kln) : tf * expf(-((float)(c - 512)) * kln);
        float pos = (c < 512) ? cosf(ph) : sinf(ph);
        float y = (v[i] - mean) * inv * g[c] + b[c] + pos;
        size_t idx = (size_t)r * C_DIM + c;
        out[idx] = y;
        __nv_bfloat16 hi, lo; split_pair(y, hi, lo);
        oh[idx] = hi; ol[idx] = lo;
    }
}

// ================= y = LN(xin+add) =================
template<int SPLIT>
__global__ __launch_bounds__(256) void add_ln_kernel(
    const float* __restrict__ xin, const float* __restrict__ add,
    const float* __restrict__ g, const float* __restrict__ b,
    float* __restrict__ out, __nv_bfloat16* __restrict__ oh, __nv_bfloat16* __restrict__ ol)
{
    __shared__ float sh[256];
    int r = blockIdx.x, tid = threadIdx.x;
    const float* xr = xin + (size_t)r * C_DIM;
    const float* ar = add + (size_t)r * C_DIM;
    float v[4]; float s = 0.f;
#pragma unroll
    for (int i = 0; i < 4; i++) { int c = tid + 256 * i; v[i] = xr[c] + ar[c]; s += v[i]; }
    float mean = blk_sum(s, sh) * (1.0f / C_DIM);
    float d2 = 0.f;
#pragma unroll
    for (int i = 0; i < 4; i++) { float d = v[i] - mean; d2 += d * d; }
    float inv = rsqrtf(blk_sum(d2, sh) * (1.0f / C_DIM) + 1e-5f);
#pragma unroll
    for (int i = 0; i < 4; i++) {
        int c = tid + 256 * i;
        float y = (v[i] - mean) * inv * g[c] + b[c];
        size_t idx = (size_t)r * C_DIM + c;
        out[idx] = y;
        if (SPLIT) { __nv_bfloat16 hi, lo; split_pair(y, hi, lo); oh[idx] = hi; ol[idx] = lo; }
    }
}

// ================= split-bf16 HMMA GEMM ===================
// CTA tile 256x128, 512 thr (16 warps: 4 M-warps x 4 N-warps, 64x32 each),
// BK=64, 2-stage cp.async (96KB/stage). 3-term bf16 MMA, fp32 accum.
// OUT_MODE 0: fp32 + bias. 1: gelu(.)->split. 2: (.)*qscale->split (QKV).
#define GEMM_SMEM_BYTES (1024 + 2 * 98304)

template<int OUT_MODE>
__global__ __launch_bounds__(512, 1) void gemm_hmma3(
    const __nv_bfloat16* __restrict__ Ah, const __nv_bfloat16* __restrict__ Al,
    const __nv_bfloat16* __restrict__ Bh, const __nv_bfloat16* __restrict__ Bl,
    const float* __restrict__ bias,
    float* __restrict__ Cf, __nv_bfloat16* __restrict__ Ch, __nv_bfloat16* __restrict__ Cl,
    int M, int N, int K)
{
    extern __shared__ char dsm[];
    const uint32_t tiles = (smem_to_u32(dsm) + 1023u) & ~1023u;
    const int tid = threadIdx.x;
    const int wid = tid >> 5;
    const int lid = tid & 31;
    const int warp_m = wid & 3;        // 4 M-warps * 64 rows
    const int warp_n = wid >> 2;       // 4 N-warps * 32 cols
    const int row0 = blockIdx.y * 256;
    const int col0 = blockIdx.x * 128;
    const int nchunk = K >> 6;

    const char* gsrc0 = (const char*)(Ah + (size_t)row0 * K);
    const char* gsrc1 = (const char*)(Al + (size_t)row0 * K);
    const char* gsrc2 = (const char*)(Bh + (size_t)col0 * K);
    const char* gsrc3 = (const char*)(Bl + (size_t)col0 * K);
    const size_t rowbytes = (size_t)K * 2;

    // stage layout: Ah[0,32K) Al[32K,64K) Bh[64K,80K) Bl[80K,96K)
    auto load_chunk = [&](int c, int st) {
        const uint32_t sb = tiles + st * 98304;
        const size_t koff = (size_t)c * 128;
#pragma unroll
        for (int i = 0; i < 12; i++) {
            int u = tid + i * 512;             // 0..6143 16B units
            int r, cb; const char* g; uint32_t sreg;
            if (u < 2048)      { r = u >> 3;            cb = (u & 7) * 16; g = gsrc0; sreg = sb; }
            else if (u < 4096) { r = (u - 2048) >> 3;   cb = (u & 7) * 16; g = gsrc1; sreg = sb + 32768; }
            else if (u < 5120) { r = (u - 4096) >> 3;   cb = (u & 7) * 16; g = gsrc2; sreg = sb + 65536; }
            else               { r = (u - 5120) >> 3;   cb = (u & 7) * 16; g = gsrc3; sreg = sb + 81920; }
            g += (size_t)r * rowbytes + koff + cb;
            CPA16(sreg + SMEM_SWIZZLE_128B((uint32_t)(r * 128 + cb)), g);
        }
        asm volatile("cp.async.commit_group;");
    };

    float acc[4][4][4];
#pragma unroll
    for (int a = 0; a < 4; a++)
#pragma unroll
        for (int b = 0; b < 4; b++)
#pragma unroll
            for (int i = 0; i < 4; i++) acc[a][b][i] = 0.f;

    const int lane15 = lid & 15;
    const int lanehi = lid >> 4;
    const int xr = lane15 & 7;

    load_chunk(0, 0);

    for (int c = 0; c < nchunk; c++) {
        const int st = c & 1;
        if (c + 1 < nchunk) {
            load_chunk(c + 1, st ^ 1);
            asm volatile("cp.async.wait_group 1;");
        } else {
            asm volatile("cp.async.wait_group 0;");
        }
        __syncthreads();

        const uint32_t sb = tiles + st * 98304;
        const uint32_t aBaseH = sb          + (uint32_t)(warp_m * 64 + lane15) * 128;
        const uint32_t aBaseL = sb + 32768  + (uint32_t)(warp_m * 64 + lane15) * 128;
        const uint32_t bBaseH = sb + 65536  + (uint32_t)(warp_n * 32 + lane15) * 128;
        const uint32_t bBaseL = sb + 81920  + (uint32_t)(warp_n * 32 + lane15) * 128;

#pragma unroll
        for (int ks = 0; ks < 4; ks++) {
            const uint32_t uoff = (uint32_t)(((ks * 2 + lanehi) ^ xr) * 16);
            uint32_t ah[4][4], al[4][4], bhv[2][4], blv[2][4];
#pragma unroll
            for (int mt = 0; mt < 4; mt++) {
                ldsm4(ah[mt], aBaseH + mt * 2048 + uoff);
                ldsm4(al[mt], aBaseL + mt * 2048 + uoff);
            }
#pragma unroll
            for (int pt = 0; pt < 2; pt++) {
                ldsm4(bhv[pt], bBaseH + pt * 2048 + uoff);
                ldsm4(blv[pt], bBaseL + pt * 2048 + uoff);
            }
#pragma unroll
            for (int mt = 0; mt < 4; mt++) {
#pragma unroll
                for (int nt = 0; nt < 4; nt++) {
                    const int pt = nt >> 1, o = nt & 1;
                    mma16816(acc[mt][nt], ah[mt], bhv[pt][o], bhv[pt][o + 2]);
                    mma16816(acc[mt][nt], ah[mt], blv[pt][o], blv[pt][o + 2]);
                    mma16816(acc[mt][nt], al[mt], bhv[pt][o], bhv[pt][o + 2]);
                }
            }
        }
        __syncthreads();
    }

    const int lr = lid >> 2;
    const int lc = (lid & 3) * 2;
#pragma unroll
    for (int mt = 0; mt < 4; mt++) {
        const int row = row0 + warp_m * 64 + mt * 16 + lr;
#pragma unroll
        for (int nt = 0; nt < 4; nt++) {
            const int col = col0 + warp_n * 32 + nt * 8 + lc;
            const float b0 = bias[col], b1 = bias[col + 1];
            float v0 = acc[mt][nt][0] + b0, v1 = acc[mt][nt][1] + b1;
            float v2 = acc[mt][nt][2] + b0, v3 = acc[mt][nt][3] + b1;
            if (OUT_MODE == 0) {
                float2 w0; w0.x = v0; w0.y = v1;
                float2 w1; w1.x = v2; w1.y = v3;
                *(float2*)(Cf + (size_t)row * N + col) = w0;
                *(float2*)(Cf + (size_t)(row + 8) * N + col) = w1;
            } else {
                if (OUT_MODE == 1) {
                    v0 = 0.5f * v0 * (1.f + erff(v0 * 0.70710678118654752f));
                    v1 = 0.5f * v1 * (1.f + erff(v1 * 0.70710678118654752f));
                    v2 = 0.5f * v2 * (1.f + erff(v2 * 0.70710678118654752f));
                    v3 = 0.5f * v3 * (1.f + erff(v3 * 0.70710678118654752f));
                } else {
                    float sc = (col < C_DIM) ? 0.125f : 1.0f;  // scale Q only
                    v0 *= sc; v1 *= sc; v2 *= sc; v3 *= sc;
                }
                __nv_bfloat16 h0, l0, h1, l1, h2, l2, h3, l3;
                split_pair(v0, h0, l0); split_pair(v1, h1, l1);
                split_pair(v2, h2, l2); split_pair(v3, h3, l3);
                __nv_bfloat162 hh0; hh0.x = h0; hh0.y = h1;
                __nv_bfloat162 ll0; ll0.x = l0; ll0.y = l1;
                __nv_bfloat162 hh1; hh1.x = h2; hh1.y = h3;
                __nv_bfloat162 ll1; ll1.x = l2; ll1.y = l3;
                *(__nv_bfloat162*)(Ch + (size_t)row * N + col) = hh0;
                *(__nv_bfloat162*)(Cl + (size_t)row * N + col) = ll0;
                *(__nv_bfloat162*)(Ch + (size_t)(row + 8) * N + col) = hh1;
                *(__nv_bfloat162*)(Cl + (size_t)(row + 8) * N + col) = ll1;
            }
        }
    }
}

// ================= HMMA flash attention (sliding window) ===================
#define ATTN_SMEM (1024 + 6 * 8192)

__global__ __launch_bounds__(128, 3) void attn_mma_kernel(
    const __nv_bfloat16* __restrict__ qkvh, const __nv_bfloat16* __restrict__ qkvl,
    const float* __restrict__ bqkv_l,
    __nv_bfloat16* __restrict__ oh, __nv_bfloat16* __restrict__ ol)
{
    extern __shared__ char dsm[];
    const uint32_t base = (smem_to_u32(dsm) + 1023u) & ~1023u;
    const uint32_t sQh = base,          sQl = base + 8192;
    const uint32_t sKh = base + 16384,  sKl = base + 24576;
    const uint32_t sVh = base + 32768,  sVl = base + 40960;

    const int tid = threadIdx.x, wid = tid >> 5, lid = tid & 31;
    const int b = blockIdx.z, h = blockIdx.y, q0 = blockIdx.x * 64;
    const int lane15 = lid & 15, lanehi = lid >> 4, xr = lane15 & 7;
    const int tig = lid & 3, gid = lid >> 2;
    const size_t RS = 3 * C_DIM;

#pragma unroll
    for (int i = 0; i < 8; i++) {
        int u = tid + i * 128;
        int half = u >> 9, idx = u & 511;
        int r = idx >> 3, cu = idx & 7;
        const char* g = (const char*)((half ? qkvl : qkvh)
                        + (size_t)(b * SEQ + q0 + r) * RS + h * HD) + cu * 16;
        uint32_t d = (half ? sQl : sQh) + (uint32_t)(r * 128 + ((cu ^ (r & 7)) * 16));
        CPA16(d, g);
    }
    asm volatile("cp.async.commit_group;");
    asm volatile("cp.async.wait_group 0;");
    __syncthreads();

    uint32_t qfh[4][4], qfl[4][4];
    {
        const uint32_t qrb = (uint32_t)((wid * 16 + lane15) * 128);
#pragma unroll
        for (int ks = 0; ks < 4; ks++) {
            const uint32_t uoff = (uint32_t)(((ks * 2 + lanehi) ^ xr) * 16);
            ldsm4(qfh[ks], sQh + qrb + uoff);
            ldsm4(qfl[ks], sQl + qrb + uoff);
        }
    }

    const int tq0 = q0 + wid * 16 + gid, tq1 = tq0 + 8;
    const float* bk = bqkv_l + C_DIM + h * HD;
    const float* bv = bqkv_l + 2 * C_DIM + h * HD;
    float sp0 = 0.f, sp1 = 0.f;
    {
        const __nv_bfloat16* q0h = qkvh + (size_t)(b * SEQ + tq0) * RS + h * HD + tig * 16;
        const __nv_bfloat16* q0l = qkvl + (size_t)(b * SEQ + tq0) * RS + h * HD + tig * 16;
        const __nv_bfloat16* q1h = qkvh + (size_t)(b * SEQ + tq1) * RS + h * HD + tig * 16;
        const __nv_bfloat16* q1l = qkvl + (size_t)(b * SEQ + tq1) * RS + h * HD + tig * 16;
#pragma unroll
        for (int dd = 0; dd < 16; dd++) {
            float w = bk[tig * 16 + dd];
            sp0 += (__bfloat162float(q0h[dd]) + __bfloat162float(q0l[dd])) * w;
            sp1 += (__bfloat162float(q1h[dd]) + __bfloat162float(q1l[dd])) * w;
        }
        sp0 += __shfl_xor_sync(0xFFFFFFFF, sp0, 1); sp0 += __shfl_xor_sync(0xFFFFFFFF, sp0, 2);
        sp1 += __shfl_xor_sync(0xFFFFFFFF, sp1, 1); sp1 += __shfl_xor_sync(0xFFFFFFFF, sp1, 2);
    }
    const bool pv0 = (tq0 <= WIN - 1), pv1 = (tq1 <= WIN - 1);
    float m0 = pv0 ? sp0 : -1e30f, m1 = pv1 ? sp1 : -1e30f;
    float l0 = pv0 ? 1.f : 0.f,     l1 = pv1 ? 1.f : 0.f;
    float o[8][4];
#pragma unroll
    for (int nt = 0; nt < 8; nt++) {
        float bva = bv[nt * 8 + 2 * tig], bvb = bv[nt * 8 + 2 * tig + 1];
        o[nt][0] = pv0 ? bva : 0.f; o[nt][1] = pv0 ? bvb : 0.f;
        o[nt][2] = pv1 ? bva : 0.f; o[nt][3] = pv1 ? bvb : 0.f;
    }

    const int jlo = (q0 > WIN) ? ((q0 - WIN) & ~63) : 0;
    for (int j0 = jlo; j0 < q0 + 64; j0 += 64) {
        __syncthreads();
#pragma unroll
        for (int i = 0; i < 16; i++) {
            int u = tid + i * 128;
            int t = u >> 9, idx = u & 511;
            int r = idx >> 3, cu = idx & 7;
            const __nv_bfloat16* arr = (t == 0 || t == 2) ? qkvh : qkvl;
            const size_t coloff = ((t < 2) ? C_DIM : 2 * C_DIM) + h * HD;
            const char* g = (const char*)(arr + (size_t)(b * SEQ + j0 + r) * RS + coloff) + cu * 16;
            uint32_t db = (t == 0 ? sKh : t == 1 ? sKl : t == 2 ? sVh : sVl);
            CPA16(db + (uint32_t)(r * 128 + ((cu ^ (r & 7)) * 16)), g);
        }
        asm volatile("cp.async.commit_group;");
        asm volatile("cp.async.wait_group 0;");
        __syncthreads();

        float s[8][4];
#pragma unroll
        for (int nt = 0; nt < 8; nt++)
#pragma unroll
            for (int i = 0; i < 4; i++) s[nt][i] = 0.f;
#pragma unroll
        for (int ks = 0; ks < 4; ks++) {
            const uint32_t uoff = (uint32_t)(((ks * 2 + lanehi) ^ xr) * 16);
            uint32_t kh[4][4], kl[4][4];
#pragma unroll
            for (int pt = 0; pt < 4; pt++) {
                ldsm4(kh[pt], sKh + (uint32_t)((pt * 16 + lane15) * 128) + uoff);
                ldsm4(kl[pt], sKl + (uint32_t)((pt * 16 + lane15) * 128) + uoff);
            }
#pragma unroll
            for (int nt = 0; nt < 8; nt++) {
                const int pt = nt >> 1, oo = nt & 1;
                mma16816(s[nt], qfh[ks], kh[pt][oo], kh[pt][oo + 2]);
                mma16816(s[nt], qfh[ks], kl[pt][oo], kl[pt][oo + 2]);
                mma16816(s[nt], qfl[ks], kh[pt][oo], kh[pt][oo + 2]);
            }
        }
#pragma unroll
        for (int nt = 0; nt < 8; nt++)
#pragma unroll
            for (int i = 0; i < 4; i++) {
                int key = j0 + nt * 8 + 2 * tig + (i & 1);
                int tq = (i < 2) ? tq0 : tq1;
                int dlt = tq - key;
                if (dlt < 0 || dlt > WIN) s[nt][i] = -3.0e38f;
            }
        float mc0 = -3.0e38f, mc1 = -3.0e38f;
#pragma unroll
        for (int nt = 0; nt < 8; nt++) {
            mc0 = fmaxf(mc0, fmaxf(s[nt][0], s[nt][1]));
            mc1 = fmaxf(mc1, fmaxf(s[nt][2], s[nt][3]));
        }
        mc0 = fmaxf(mc0, __shfl_xor_sync(0xFFFFFFFF, mc0, 1));
        mc0 = fmaxf(mc0, __shfl_xor_sync(0xFFFFFFFF, mc0, 2));
        mc1 = fmaxf(mc1, __shfl_xor_sync(0xFFFFFFFF, mc1, 1));
        mc1 = fmaxf(mc1, __shfl_xor_sync(0xFFFFFFFF, mc1, 2));
        float mn0 = fmaxf(m0, mc0), mn1 = fmaxf(m1, mc1);
        float a0 = __expf(m0 - mn0), a1 = __expf(m1 - mn1);
        float rs0 = 0.f, rs1 = 0.f;
#pragma unroll
        for (int nt = 0; nt < 8; nt++) {
            s[nt][0] = __expf(s[nt][0] - mn0); rs0 += s[nt][0];
            s[nt][1] = __expf(s[nt][1] - mn0); rs0 += s[nt][1];
            s[nt][2] = __expf(s[nt][2] - mn1); rs1 += s[nt][2];
            s[nt][3] = __expf(s[nt][3] - mn1); rs1 += s[nt][3];
        }
        rs0 += __shfl_xor_sync(0xFFFFFFFF, rs0, 1); rs0 += __shfl_xor_sync(0xFFFFFFFF, rs0, 2);
        rs1 += __shfl_xor_sync(0xFFFFFFFF, rs1, 1); rs1 += __shfl_xor_sync(0xFFFFFFFF, rs1, 2);
        l0 = l0 * a0 + rs0; l1 = l1 * a1 + rs1;
        m0 = mn0; m1 = mn1;
#pragma unroll
        for (int nt = 0; nt < 8; nt++) {
            o[nt][0] *= a0; o[nt][1] *= a0; o[nt][2] *= a1; o[nt][3] *= a1;
        }
        uint32_t pa[4][4];
#pragma unroll
        for (int kt = 0; kt < 4; kt++) {
            pa[kt][0] = packbf(s[2 * kt][0],     s[2 * kt][1]);
            pa[kt][1] = packbf(s[2 * kt][2],     s[2 * kt][3]);
            pa[kt][2] = packbf(s[2 * kt + 1][0], s[2 * kt + 1][1]);
            pa[kt][3] = packbf(s[2 * kt + 1][2], s[2 * kt + 1][3]);
        }
#pragma unroll
        for (int kt = 0; kt < 4; kt++) {
            const uint32_t vrb = (uint32_t)((kt * 16 + lane15) * 128);
            uint32_t vh[4][4], vl[4][4];
#pragma unroll
            for (int j = 0; j < 4; j++) {
                const uint32_t uo = (uint32_t)(((j * 2 + lanehi) ^ xr) * 16);
                ldsm4t(vh[j], sVh + vrb + uo);
                ldsm4t(vl[j], sVl + vrb + uo);
            }
#pragma unroll
            for (int j = 0; j < 4; j++) {
                mma16816(o[2 * j],     pa[kt], vh[j][0], vh[j][1]);
                mma16816(o[2 * j + 1], pa[kt], vh[j][2], vh[j][3]);
                mma16816(o[2 * j],     pa[kt], vl[j][0], vl[j][1]);
                mma16816(o[2 * j + 1], pa[kt], vl[j][2], vl[j][3]);
            }
        }
    }

    const float r0 = 1.f / l0, r1 = 1.f / l1;
#pragma unroll
    for (int nt = 0; nt < 8; nt++) {
        const int col = h * HD + nt * 8 + 2 * tig;
        float v0 = o[nt][0] * r0, v1 = o[nt][1] * r0;
        float v2 = o[nt][2] * r1, v3 = o[nt][3] * r1;
        __nv_bfloat16 h0, lo0, h1, lo1, h2, lo2, h3, lo3;
        split_pair(v0, h0, lo0); split_pair(v1, h1, lo1);
        split_pair(v2, h2, lo2); split_pair(v3, h3, lo3);
        __nv_bfloat162 hh0; hh0.x = h0; hh0.y = h1;
        __nv_bfloat162 ll0; ll0.x = lo0; ll0.y = lo1;
        __nv_bfloat162 hh1; hh1.x = h2; hh1.y = h3;
        __nv_bfloat162 ll1; ll1.x = lo2; ll1.y = lo3;
        *(__nv_bfloat162*)(oh + (size_t)(b * SEQ + tq0) * C_DIM + col) = hh0;
        *(__nv_bfloat162*)(ol + (size_t)(b * SEQ + tq0) * C_DIM + col) = ll0;
        *(__nv_bfloat162*)(oh + (size_t)(b * SEQ + tq1) * C_DIM + col) = hh1;
        *(__nv_bfloat162*)(ol + (size_t)(b * SEQ + tq1) * C_DIM + col) = ll1;
    }
}

// ================= launcher =================
extern "C" void kernel_launch(void* const* d_in, const int* in_sizes, int n_in,
                              void* d_out, int out_size)
{
    const float* x      = (const float*)d_in[0];
    const float* norm_g = (const float*)d_in[1];
    const float* norm_b = (const float*)d_in[2];
    const float* Wqkv   = (const float*)d_in[3];
    const float* bqkv   = (const float*)d_in[4];
    const float* Wo     = (const float*)d_in[5];
    const float* bo     = (const float*)d_in[6];
    const float* ln1_g  = (const float*)d_in[7];
    const float* ln1_b  = (const float*)d_in[8];
    const float* ln2_g  = (const float*)d_in[9];
    const float* ln2_b  = (const float*)d_in[10];
    const float* W1     = (const float*)d_in[11];
    const float* b1     = (const float*)d_in[12];
    const float* W2     = (const float*)d_in[13];
    const float* b2     = (const float*)d_in[14];
    float* out = (float*)d_out;

    float *gx, *gtmp;
    __nv_bfloat16 *gxh, *gxl, *gah, *gal, *ghh, *ghl, *gwh, *gwl, *gqh, *gql, *gvh, *gvl;
    cudaGetSymbolAddress((void**)&gx,   g_x);
    cudaGetSymbolAddress((void**)&gtmp, g_tmp);
    cudaGetSymbolAddress((void**)&gxh,  g_xh);  cudaGetSymbolAddress((void**)&gxl, g_xl);
    cudaGetSymbolAddress((void**)&gah,  g_ah);  cudaGetSymbolAddress((void**)&gal, g_al);
    cudaGetSymbolAddress((void**)&ghh,  g_hh);  cudaGetSymbolAddress((void**)&ghl, g_hl);
    cudaGetSymbolAddress((void**)&gwh,  g_wh);  cudaGetSymbolAddress((void**)&gwl, g_wl);
    cudaGetSymbolAddress((void**)&gqh,  g_qkvh); cudaGetSymbolAddress((void**)&gql, g_qkvl);
    cudaGetSymbolAddress((void**)&gvh,  g_vh);  cudaGetSymbolAddress((void**)&gvl, g_vl);

    cudaFuncSetAttribute(gemm_hmma3<0>, cudaFuncAttributeMaxDynamicSharedMemorySize, GEMM_SMEM_BYTES);
    cudaFuncSetAttribute(gemm_hmma3<1>, cudaFuncAttributeMaxDynamicSharedMemorySize, GEMM_SMEM_BYTES);
    cudaFuncSetAttribute(gemm_hmma3<2>, cudaFuncAttributeMaxDynamicSharedMemorySize, GEMM_SMEM_BYTES);
    cudaFuncSetAttribute(attn_mma_kernel, cudaFuncAttributeMaxDynamicSharedMemorySize, ATTN_SMEM);

    const int CONV_BLK = 592;

    embed_ln_kernel<<<NROWS, 256>>>(x, norm_g, norm_b, gx, gxh, gxl);

    for (int l = 0; l < N_LAYERS; l++) {
        const size_t oQ = (size_t)l * 3 * C_DIM * C_DIM;
        const size_t oO = (size_t)l * C_DIM * C_DIM;
        const size_t o1 = (size_t)l * HID_DIM * C_DIM;
        const size_t o2 = (size_t)l * C_DIM * HID_DIM;
        const float* bqkv_l = bqkv + (size_t)l * 3 * C_DIM;

        // split QKV weights, then Wo weights (dedicated buffer) -> gemmQKV is launch #4
        split_f32_kernel<<<CONV_BLK, 256>>>(Wqkv + oQ, gwh, gwl, 3 * C_DIM * C_DIM);
        split_f32_kernel<<<CONV_BLK, 256>>>(Wo + oO, gvh, gvl, C_DIM * C_DIM);

        // qkv = (x @ Wqkv^T + bqkv), Q scaled by 1/8, split-bf16 out
        gemm_hmma3<2><<<dim3(3 * C_DIM / 128, NROWS / 256), 512, GEMM_SMEM_BYTES>>>(
            gxh, gxl, gwh, gwl, bqkv_l, nullptr, gqh, gql,
            NROWS, 3 * C_DIM, C_DIM);

        // HMMA flash attention -> split-bf16
        attn_mma_kernel<<<dim3(SEQ / 64, N_HEADS, BATCH), 128, ATTN_SMEM>>>(
            gqh, gql, bqkv_l, gah, gal);

        // o = attn @ Wo^T + bo
        gemm_hmma3<0><<<dim3(C_DIM / 128, NROWS / 256), 512, GEMM_SMEM_BYTES>>>(
            gah, gal, gvh, gvl, bo + (size_t)l * C_DIM, gtmp, nullptr, nullptr,
            NROWS, C_DIM, C_DIM);

        // x = LN(x + o; ln1)
        add_ln_kernel<1><<<NROWS, 256>>>(gx, gtmp, ln1_g + l * C_DIM, ln1_b + l * C_DIM, gx, gxh, gxl);

        // hid = gelu(x @ W1^T + b1) -> split
        split_f32_kernel<<<CONV_BLK, 256>>>(W1 + o1, gwh, gwl, HID_DIM * C_DIM);
        gemm_hmma3<1><<<dim3(HID_DIM / 128, NROWS / 256), 512, GEMM_SMEM_BYTES>>>(
            gxh, gxl, gwh, gwl, b1 + (size_t)l * HID_DIM, nullptr, ghh, ghl,
            NROWS, HID_DIM, C_DIM);

        // ff = hid @ W2^T + b2
        split_f32_kernel<<<CONV_BLK, 256>>>(W2 + o2, gwh, gwl, C_DIM * HID_DIM);
        gemm_hmma3<0><<<dim3(C_DIM / 128, NROWS / 256), 512, GEMM_SMEM_BYTES>>>(
            ghh, ghl, gwh, gwl, b2 + (size_t)l * C_DIM, gtmp, nullptr, nullptr,
            NROWS, C_DIM, HID_DIM);

        // x = LN(x + ff; ln2)
        if (l == N_LAYERS - 1)
            add_ln_kernel<0><<<NROWS, 256>>>(gx, gtmp, ln2_g + l * C_DIM, ln2_b + l * C_DIM, out, nullptr, nullptr);
        else
            add_ln_kernel<1><<<NROWS, 256>>>(gx, gtmp, ln2_g + l * C_DIM, ln2_b + l * C_DIM, gx, gxh, gxl);
    }
}

// round 11
// speedup vs baseline: 1.4880x; 1.4880x over previous
#include <cuda_runtime.h>
#include <cuda_fp16.h>
#include <math.h>
#include <stdint.h>

#define C_DIM   1024
#define N_HEADS 16
#define HD      64
#define N_LAYERS 6
#define HID_DIM 4096
#define BATCH   2
#define SEQ     2048
#define NROWS   (BATCH*SEQ)
#define WIN     1000

// ================= scratch (no allocations allowed) =================
__device__ float g_x   [NROWS * C_DIM];
__device__ float g_tmp [NROWS * C_DIM];
__device__ __half g_xh[NROWS * C_DIM];
__device__ __half g_ah[NROWS * C_DIM];
__device__ __half g_hh[NROWS * HID_DIM];
__device__ __half g_qkvh[NROWS * 3 * C_DIM], g_qkvl[NROWS * 3 * C_DIM];
// per-layer split weight staging (reused; max 4M elems) + dedicated Wo staging
#define WMAX (HID_DIM * C_DIM)
__device__ __half g_wh[WMAX], g_wl[WMAX];
__device__ __half g_vh[C_DIM * C_DIM], g_vl[C_DIM * C_DIM];

// ================= helpers =================
__device__ __forceinline__ uint32_t smem_to_u32(const void* p) {
    uint32_t a;
    asm("{ .reg .u64 t; cvta.to.shared.u64 t, %1; cvt.u32.u64 %0, t; }" : "=r"(a) : "l"(p));
    return a;
}
#define SMEM_SWIZZLE_128B(x) ((x) ^ (((x) >> 3) & 0x70))

__device__ __forceinline__ void ldsm4(uint32_t* r, uint32_t addr) {
    asm volatile("ldmatrix.sync.aligned.m8n8.x4.shared.b16 {%0,%1,%2,%3}, [%4];"
                 : "=r"(r[0]), "=r"(r[1]), "=r"(r[2]), "=r"(r[3]) : "r"(addr));
}
__device__ __forceinline__ void ldsm4t(uint32_t* r, uint32_t addr) {
    asm volatile("ldmatrix.sync.aligned.m8n8.x4.trans.shared.b16 {%0,%1,%2,%3}, [%4];"
                 : "=r"(r[0]), "=r"(r[1]), "=r"(r[2]), "=r"(r[3]) : "r"(addr));
}
__device__ __forceinline__ void mma16816(float* d, const uint32_t* a, uint32_t b0, uint32_t b1) {
    asm volatile("mma.sync.aligned.m16n8k16.row.col.f32.f16.f16.f32 "
                 "{%0,%1,%2,%3}, {%4,%5,%6,%7}, {%8,%9}, {%0,%1,%2,%3};"
                 : "+f"(d[0]), "+f"(d[1]), "+f"(d[2]), "+f"(d[3])
                 : "r"(a[0]), "r"(a[1]), "r"(a[2]), "r"(a[3]), "r"(b0), "r"(b1));
}
__device__ __forceinline__ uint32_t packh(float lo, float hi) {
    uint32_t r;
    asm("cvt.rn.f16x2.f32 %0, %1, %2;" : "=r"(r) : "f"(hi), "f"(lo));
    return r;
}
__device__ __forceinline__ void split_pair(float v, __half& hi, __half& lo) {
    hi = __float2half_rn(v);
    lo = __float2half_rn(v - __half2float(hi));
}
#define CPA16(dst, src) \
    asm volatile("cp.async.cg.shared.global [%0], [%1], 16;" :: "r"(dst), "l"(src))

// ================= weight split kernel =================
__global__ void split_f32_kernel(const float* __restrict__ w, __half* __restrict__ h,
                                 __half* __restrict__ l, int n) {
    int i = blockIdx.x * blockDim.x + threadIdx.x;
    int stride = gridDim.x * blockDim.x;
    for (; i < n; i += stride) {
        float v = w[i];
        __half hi, lo;
        split_pair(v, hi, lo);
        h[i] = hi; l[i] = lo;
    }
}

// ================= block reduce =================
__device__ __forceinline__ float blk_sum(float v, float* sh) {
    int tid = threadIdx.x;
    sh[tid] = v; __syncthreads();
#pragma unroll
    for (int s = 128; s > 0; s >>= 1) { if (tid < s) sh[tid] += sh[tid + s]; __syncthreads(); }
    float r = sh[0]; __syncthreads();
    return r;
}

// ================= input LN + positional embedding =================
__global__ __launch_bounds__(256) void embed_ln_kernel(
    const float* __restrict__ x, const float* __restrict__ g, const float* __restrict__ b,
    float* __restrict__ out, __half* __restrict__ oh)
{
    __shared__ float sh[256];
    int r = blockIdx.x, t = r % SEQ, tid = threadIdx.x;
    const float* xr = x + (size_t)r * C_DIM;
    float v[4]; float s = 0.f;
#pragma unroll
    for (int i = 0; i < 4; i++) { v[i] = xr[tid + 256 * i]; s += v[i]; }
    float mean = blk_sum(s, sh) * (1.0f / C_DIM);
    float d2 = 0.f;
#pragma unroll
    for (int i = 0; i < 4; i++) { float d = v[i] - mean; d2 += d * d; }
    float inv = rsqrtf(blk_sum(d2, sh) * (1.0f / C_DIM) + 1e-5f);
    const float kln = 9.2103403719761836f / 511.0f;
    float tf = (float)t;
#pragma unroll
    for (int i = 0; i < 4; i++) {
        int c = tid + 256 * i;
        float ph = (c < 512) ? tf * expf(-((float)c) * kln) : tf * expf(-((float)(c - 512)) * kln);
        float pos = (c < 512) ? cosf(ph) : sinf(ph);
        float y = (v[i] - mean) * inv * g[c] + b[c] + pos;
        size_t idx = (size_t)r * C_DIM + c;
        out[idx] = y;
        oh[idx] = __float2half_rn(y);
    }
}

// ================= y = LN(xin+add) =================
template<int SPLIT>
__global__ __launch_bounds__(256) void add_ln_kernel(
    const float* __restrict__ xin, const float* __restrict__ add,
    const float* __restrict__ g, const float* __restrict__ b,
    float* __restrict__ out, __half* __restrict__ oh)
{
    __shared__ float sh[256];
    int r = blockIdx.x, tid = threadIdx.x;
    const float* xr = xin + (size_t)r * C_DIM;
    const float* ar = add + (size_t)r * C_DIM;
    float v[4]; float s = 0.f;
#pragma unroll
    for (int i = 0; i < 4; i++) { int c = tid + 256 * i; v[i] = xr[c] + ar[c]; s += v[i]; }
    float mean = blk_sum(s, sh) * (1.0f / C_DIM);
    float d2 = 0.f;
#pragma unroll
    for (int i = 0; i < 4; i++) { float d = v[i] - mean; d2 += d * d; }
    float inv = rsqrtf(blk_sum(d2, sh) * (1.0f / C_DIM) + 1e-5f);
#pragma unroll
    for (int i = 0; i < 4; i++) {
        int c = tid + 256 * i;
        float y = (v[i] - mean) * inv * g[c] + b[c];
        size_t idx = (size_t)r * C_DIM + c;
        out[idx] = y;
        if (SPLIT) oh[idx] = __float2half_rn(y);
    }
}

// ================= fp16 2-pass HMMA GEMM ===================
// C[M,N] = Ah[M,K] * (Bh+Bl)[N,K]^T + bias   (A-side lo dropped: 2^-11 residual)
// CTA tile 128x128, 256 thr (8 warps 2Mx4N, warp 64x32), BK=64, 2-stage cp.async,
// 2 CTAs/SM. Stage = Ah(16K) | Bh(16K) | Bl(16K) = 48KB.
// OUT_MODE 0: fp32 + bias. 1: gelu(.)->fp16 hi. 2: (.)*qscale->fp16 hi+lo (QKV).
#define GEMM_SMEM_BYTES (1024 + 2 * 49152)

template<int OUT_MODE>
__global__ __launch_bounds__(256, 2) void gemm_hmma2(
    const __half* __restrict__ Ah,
    const __half* __restrict__ Bh, const __half* __restrict__ Bl,
    const float* __restrict__ bias,
    float* __restrict__ Cf, __half* __restrict__ Ch, __half* __restrict__ Cl,
    int M, int N, int K)
{
    extern __shared__ char dsm[];
    const uint32_t tiles = (smem_to_u32(dsm) + 1023u) & ~1023u;
    const int tid = threadIdx.x;
    const int wid = tid >> 5;
    const int lid = tid & 31;
    const int warp_m = wid & 1;        // 2 M-warps * 64 rows
    const int warp_n = wid >> 1;       // 4 N-warps * 32 cols
    const int row0 = blockIdx.y * 128;
    const int col0 = blockIdx.x * 128;
    const int nchunk = K >> 6;

    const char* gsrc0 = (const char*)(Ah + (size_t)row0 * K);
    const char* gsrc1 = (const char*)(Bh + (size_t)col0 * K);
    const char* gsrc2 = (const char*)(Bl + (size_t)col0 * K);
    const size_t rowbytes = (size_t)K * 2;

    auto load_chunk = [&](int c, int st) {
        const uint32_t sb = tiles + st * 49152;
        const size_t koff = (size_t)c * 128;
#pragma unroll
        for (int i = 0; i < 12; i++) {
            int u = tid + i * 256;             // 0..3071 16B units
            int r, cb; const char* g; uint32_t sreg;
            if (u < 1024)      { r = u >> 3;          cb = (u & 7) * 16; g = gsrc0; sreg = sb; }
            else if (u < 2048) { r = (u - 1024) >> 3; cb = (u & 7) * 16; g = gsrc1; sreg = sb + 16384; }
            else               { r = (u - 2048) >> 3; cb = (u & 7) * 16; g = gsrc2; sreg = sb + 32768; }
            g += (size_t)r * rowbytes + koff + cb;
            CPA16(sreg + SMEM_SWIZZLE_128B((uint32_t)(r * 128 + cb)), g);
        }
        asm volatile("cp.async.commit_group;");
    };

    float acc[4][4][4];
#pragma unroll
    for (int a = 0; a < 4; a++)
#pragma unroll
        for (int b = 0; b < 4; b++)
#pragma unroll
            for (int i = 0; i < 4; i++) acc[a][b][i] = 0.f;

    const int lane15 = lid & 15;
    const int lanehi = lid >> 4;
    const int xr = lane15 & 7;

    load_chunk(0, 0);

    for (int c = 0; c < nchunk; c++) {
        const int st = c & 1;
        if (c + 1 < nchunk) {
            load_chunk(c + 1, st ^ 1);
            asm volatile("cp.async.wait_group 1;");
        } else {
            asm volatile("cp.async.wait_group 0;");
        }
        __syncthreads();

        const uint32_t sb = tiles + st * 49152;
        const uint32_t aBase  = sb          + (uint32_t)(warp_m * 64 + lane15) * 128;
        const uint32_t bBaseH = sb + 16384  + (uint32_t)(warp_n * 32 + lane15) * 128;
        const uint32_t bBaseL = sb + 32768  + (uint32_t)(warp_n * 32 + lane15) * 128;

#pragma unroll
        for (int ks = 0; ks < 4; ks++) {
            const uint32_t uoff = (uint32_t)(((ks * 2 + lanehi) ^ xr) * 16);
            uint32_t ah[4][4], bhv[2][4], blv[2][4];
#pragma unroll
            for (int mt = 0; mt < 4; mt++)
                ldsm4(ah[mt], aBase + mt * 2048 + uoff);
#pragma unroll
            for (int pt = 0; pt < 2; pt++) {
                ldsm4(bhv[pt], bBaseH + pt * 2048 + uoff);
                ldsm4(blv[pt], bBaseL + pt * 2048 + uoff);
            }
#pragma unroll
            for (int mt = 0; mt < 4; mt++) {
#pragma unroll
                for (int nt = 0; nt < 4; nt++) {
                    const int pt = nt >> 1, o = nt & 1;
                    mma16816(acc[mt][nt], ah[mt], bhv[pt][o], bhv[pt][o + 2]);
                    mma16816(acc[mt][nt], ah[mt], blv[pt][o], blv[pt][o + 2]);
                }
            }
        }
        __syncthreads();
    }

    const int lr = lid >> 2;
    const int lc = (lid & 3) * 2;
#pragma unroll
    for (int mt = 0; mt < 4; mt++) {
        const int row = row0 + warp_m * 64 + mt * 16 + lr;
#pragma unroll
        for (int nt = 0; nt < 4; nt++) {
            const int col = col0 + warp_n * 32 + nt * 8 + lc;
            const float b0 = bias[col], b1 = bias[col + 1];
            float v0 = acc[mt][nt][0] + b0, v1 = acc[mt][nt][1] + b1;
            float v2 = acc[mt][nt][2] + b0, v3 = acc[mt][nt][3] + b1;
            if (OUT_MODE == 0) {
                float2 w0; w0.x = v0; w0.y = v1;
                float2 w1; w1.x = v2; w1.y = v3;
                *(float2*)(Cf + (size_t)row * N + col) = w0;
                *(float2*)(Cf + (size_t)(row + 8) * N + col) = w1;
            } else if (OUT_MODE == 1) {
                v0 = 0.5f * v0 * (1.f + erff(v0 * 0.70710678118654752f));
                v1 = 0.5f * v1 * (1.f + erff(v1 * 0.70710678118654752f));
                v2 = 0.5f * v2 * (1.f + erff(v2 * 0.70710678118654752f));
                v3 = 0.5f * v3 * (1.f + erff(v3 * 0.70710678118654752f));
                __half2 hh0 = __floats2half2_rn(v0, v1);
                __half2 hh1 = __floats2half2_rn(v2, v3);
                *(__half2*)(Ch + (size_t)row * N + col) = hh0;
                *(__half2*)(Ch + (size_t)(row + 8) * N + col) = hh1;
            } else {
                float sc = (col < C_DIM) ? 0.125f : 1.0f;  // scale Q only
                v0 *= sc; v1 *= sc; v2 *= sc; v3 *= sc;
                __half h0, l0, h1, l1, h2, l2, h3, l3;
                split_pair(v0, h0, l0); split_pair(v1, h1, l1);
                split_pair(v2, h2, l2); split_pair(v3, h3, l3);
                __half2 hh0; hh0.x = h0; hh0.y = h1;
                __half2 ll0; ll0.x = l0; ll0.y = l1;
                __half2 hh1; hh1.x = h2; hh1.y = h3;
                __half2 ll1; ll1.x = l2; ll1.y = l3;
                *(__half2*)(Ch + (size_t)row * N + col) = hh0;
                *(__half2*)(Cl + (size_t)row * N + col) = ll0;
                *(__half2*)(Ch + (size_t)(row + 8) * N + col) = hh1;
                *(__half2*)(Cl + (size_t)(row + 8) * N + col) = ll1;
            }
        }
    }
}

// ================= fp16 HMMA flash attention (sliding window) ===================
// S = QhKh + QhKl + QlKh (fp16 split, residual 2^-22); P fp16; O += P*(Vh+Vl).
#define ATTN_SMEM (1024 + 6 * 8192)

__global__ __launch_bounds__(128, 3) void attn_mma_kernel(
    const __half* __restrict__ qkvh, const __half* __restrict__ qkvl,
    const float* __restrict__ bqkv_l,
    __half* __restrict__ oh)
{
    extern __shared__ char dsm[];
    const uint32_t base = (smem_to_u32(dsm) + 1023u) & ~1023u;
    const uint32_t sQh = base,          sQl = base + 8192;
    const uint32_t sKh = base + 16384,  sKl = base + 24576;
    const uint32_t sVh = base + 32768,  sVl = base + 40960;

    const int tid = threadIdx.x, wid = tid >> 5, lid = tid & 31;
    const int b = blockIdx.z, h = blockIdx.y, q0 = blockIdx.x * 64;
    const int lane15 = lid & 15, lanehi = lid >> 4, xr = lane15 & 7;
    const int tig = lid & 3, gid = lid >> 2;
    const size_t RS = 3 * C_DIM;

#pragma unroll
    for (int i = 0; i < 8; i++) {
        int u = tid + i * 128;
        int half = u >> 9, idx = u & 511;
        int r = idx >> 3, cu = idx & 7;
        const char* g = (const char*)((half ? qkvl : qkvh)
                        + (size_t)(b * SEQ + q0 + r) * RS + h * HD) + cu * 16;
        uint32_t d = (half ? sQl : sQh) + (uint32_t)(r * 128 + ((cu ^ (r & 7)) * 16));
        CPA16(d, g);
    }
    asm volatile("cp.async.commit_group;");
    asm volatile("cp.async.wait_group 0;");
    __syncthreads();

    uint32_t qfh[4][4], qfl[4][4];
    {
        const uint32_t qrb = (uint32_t)((wid * 16 + lane15) * 128);
#pragma unroll
        for (int ks = 0; ks < 4; ks++) {
            const uint32_t uoff = (uint32_t)(((ks * 2 + lanehi) ^ xr) * 16);
            ldsm4(qfh[ks], sQh + qrb + uoff);
            ldsm4(qfl[ks], sQl + qrb + uoff);
        }
    }

    const int tq0 = q0 + wid * 16 + gid, tq1 = tq0 + 8;
    const float* bk = bqkv_l + C_DIM + h * HD;
    const float* bv = bqkv_l + 2 * C_DIM + h * HD;
    float sp0 = 0.f, sp1 = 0.f;
    {
        const __half* q0h = qkvh + (size_t)(b * SEQ + tq0) * RS + h * HD + tig * 16;
        const __half* q0l = qkvl + (size_t)(b * SEQ + tq0) * RS + h * HD + tig * 16;
        const __half* q1h = qkvh + (size_t)(b * SEQ + tq1) * RS + h * HD + tig * 16;
        const __half* q1l = qkvl + (size_t)(b * SEQ + tq1) * RS + h * HD + tig * 16;
#pragma unroll
        for (int dd = 0; dd < 16; dd++) {
            float w = bk[tig * 16 + dd];
            sp0 += (__half2float(q0h[dd]) + __half2float(q0l[dd])) * w;
            sp1 += (__half2float(q1h[dd]) + __half2float(q1l[dd])) * w;
        }
        sp0 += __shfl_xor_sync(0xFFFFFFFF, sp0, 1); sp0 += __shfl_xor_sync(0xFFFFFFFF, sp0, 2);
        sp1 += __shfl_xor_sync(0xFFFFFFFF, sp1, 1); sp1 += __shfl_xor_sync(0xFFFFFFFF, sp1, 2);
    }
    const bool pv0 = (tq0 <= WIN - 1), pv1 = (tq1 <= WIN - 1);
    float m0 = pv0 ? sp0 : -1e30f, m1 = pv1 ? sp1 : -1e30f;
    float l0 = pv0 ? 1.f : 0.f,     l1 = pv1 ? 1.f : 0.f;
    float o[8][4];
#pragma unroll
    for (int nt = 0; nt < 8; nt++) {
        float bva = bv[nt * 8 + 2 * tig], bvb = bv[nt * 8 + 2 * tig + 1];
        o[nt][0] = pv0 ? bva : 0.f; o[nt][1] = pv0 ? bvb : 0.f;
        o[nt][2] = pv1 ? bva : 0.f; o[nt][3] = pv1 ? bvb : 0.f;
    }

    const int jlo = (q0 > WIN) ? ((q0 - WIN) & ~63) : 0;
    for (int j0 = jlo; j0 < q0 + 64; j0 += 64) {
        __syncthreads();
#pragma unroll
        for (int i = 0; i < 16; i++) {
            int u = tid + i * 128;
            int t = u >> 9, idx = u & 511;
            int r = idx >> 3, cu = idx & 7;
            const __half* arr = (t == 0 || t == 2) ? qkvh : qkvl;
            const size_t coloff = ((t < 2) ? C_DIM : 2 * C_DIM) + h * HD;
            const char* g = (const char*)(arr + (size_t)(b * SEQ + j0 + r) * RS + coloff) + cu * 16;
            uint32_t db = (t == 0 ? sKh : t == 1 ? sKl : t == 2 ? sVh : sVl);
            CPA16(db + (uint32_t)(r * 128 + ((cu ^ (r & 7)) * 16)), g);
        }
        asm volatile("cp.async.commit_group;");
        asm volatile("cp.async.wait_group 0;");
        __syncthreads();

        float s[8][4];
#pragma unroll
        for (int nt = 0; nt < 8; nt++)
#pragma unroll
            for (int i = 0; i < 4; i++) s[nt][i] = 0.f;
#pragma unroll
        for (int ks = 0; ks < 4; ks++) {
            const uint32_t uoff = (uint32_t)(((ks * 2 + lanehi) ^ xr) * 16);
            uint32_t kh[4][4], kl[4][4];
#pragma unroll
            for (int pt = 0; pt < 4; pt++) {
                ldsm4(kh[pt], sKh + (uint32_t)((pt * 16 + lane15) * 128) + uoff);
                ldsm4(kl[pt], sKl + (uint32_t)((pt * 16 + lane15) * 128) + uoff);
            }
#pragma unroll
            for (int nt = 0; nt < 8; nt++) {
                const int pt = nt >> 1, oo = nt & 1;
                mma16816(s[nt], qfh[ks], kh[pt][oo], kh[pt][oo + 2]);
                mma16816(s[nt], qfh[ks], kl[pt][oo], kl[pt][oo + 2]);
                mma16816(s[nt], qfl[ks], kh[pt][oo], kh[pt][oo + 2]);
            }
        }
#pragma unroll
        for (int nt = 0; nt < 8; nt++)
#pragma unroll
            for (int i = 0; i < 4; i++) {
                int key = j0 + nt * 8 + 2 * tig + (i & 1);
                int tq = (i < 2) ? tq0 : tq1;
                int dlt = tq - key;
                if (dlt < 0 || dlt > WIN) s[nt][i] = -3.0e38f;
            }
        float mc0 = -3.0e38f, mc1 = -3.0e38f;
#pragma unroll
        for (int nt = 0; nt < 8; nt++) {
            mc0 = fmaxf(mc0, fmaxf(s[nt][0], s[nt][1]));
            mc1 = fmaxf(mc1, fmaxf(s[nt][2], s[nt][3]));
        }
        mc0 = fmaxf(mc0, __shfl_xor_sync(0xFFFFFFFF, mc0, 1));
        mc0 = fmaxf(mc0, __shfl_xor_sync(0xFFFFFFFF, mc0, 2));
        mc1 = fmaxf(mc1, __shfl_xor_sync(0xFFFFFFFF, mc1, 1));
        mc1 = fmaxf(mc1, __shfl_xor_sync(0xFFFFFFFF, mc1, 2));
        float mn0 = fmaxf(m0, mc0), mn1 = fmaxf(m1, mc1);
        float a0 = __expf(m0 - mn0), a1 = __expf(m1 - mn1);
        float rs0 = 0.f, rs1 = 0.f;
#pragma unroll
        for (int nt = 0; nt < 8; nt++) {
            s[nt][0] = __expf(s[nt][0] - mn0); rs0 += s[nt][0];
            s[nt][1] = __expf(s[nt][1] - mn0); rs0 += s[nt][1];
            s[nt][2] = __expf(s[nt][2] - mn1); rs1 += s[nt][2];
            s[nt][3] = __expf(s[nt][3] - mn1); rs1 += s[nt][3];
        }
        rs0 += __shfl_xor_sync(0xFFFFFFFF, rs0, 1); rs0 += __shfl_xor_sync(0xFFFFFFFF, rs0, 2);
        rs1 += __shfl_xor_sync(0xFFFFFFFF, rs1, 1); rs1 += __shfl_xor_sync(0xFFFFFFFF, rs1, 2);
        l0 = l0 * a0 + rs0; l1 = l1 * a1 + rs1;
        m0 = mn0; m1 = mn1;
#pragma unroll
        for (int nt = 0; nt < 8; nt++) {
            o[nt][0] *= a0; o[nt][1] *= a0; o[nt][2] *= a1; o[nt][3] *= a1;
        }
        uint32_t pa[4][4];
#pragma unroll
        for (int kt = 0; kt < 4; kt++) {
            pa[kt][0] = packh(s[2 * kt][0],     s[2 * kt][1]);
            pa[kt][1] = packh(s[2 * kt][2],     s[2 * kt][3]);
            pa[kt][2] = packh(s[2 * kt + 1][0], s[2 * kt + 1][1]);
            pa[kt][3] = packh(s[2 * kt + 1][2], s[2 * kt + 1][3]);
        }
#pragma unroll
        for (int kt = 0; kt < 4; kt++) {
            const uint32_t vrb = (uint32_t)((kt * 16 + lane15) * 128);
            uint32_t vh[4][4], vl[4][4];
#pragma unroll
            for (int j = 0; j < 4; j++) {
                const uint32_t uo = (uint32_t)(((j * 2 + lanehi) ^ xr) * 16);
                ldsm4t(vh[j], sVh + vrb + uo);
                ldsm4t(vl[j], sVl + vrb + uo);
            }
#pragma unroll
            for (int j = 0; j < 4; j++) {
                mma16816(o[2 * j],     pa[kt], vh[j][0], vh[j][1]);
                mma16816(o[2 * j + 1], pa[kt], vh[j][2], vh[j][3]);
                mma16816(o[2 * j],     pa[kt], vl[j][0], vl[j][1]);
                mma16816(o[2 * j + 1], pa[kt], vl[j][2], vl[j][3]);
            }
        }
    }

    const float r0 = 1.f / l0, r1 = 1.f / l1;
#pragma unroll
    for (int nt = 0; nt < 8; nt++) {
        const int col = h * HD + nt * 8 + 2 * tig;
        __half2 hh0 = __floats2half2_rn(o[nt][0] * r0, o[nt][1] * r0);
        __half2 hh1 = __floats2half2_rn(o[nt][2] * r1, o[nt][3] * r1);
        *(__half2*)(oh + (size_t)(b * SEQ + tq0) * C_DIM + col) = hh0;
        *(__half2*)(oh + (size_t)(b * SEQ + tq1) * C_DIM + col) = hh1;
    }
}

// ================= launcher =================
extern "C" void kernel_launch(void* const* d_in, const int* in_sizes, int n_in,
                              void* d_out, int out_size)
{
    const float* x      = (const float*)d_in[0];
    const float* norm_g = (const float*)d_in[1];
    const float* norm_b = (const float*)d_in[2];
    const float* Wqkv   = (const float*)d_in[3];
    const float* bqkv   = (const float*)d_in[4];
    const float* Wo     = (const float*)d_in[5];
    const float* bo     = (const float*)d_in[6];
    const float* ln1_g  = (const float*)d_in[7];
    const float* ln1_b  = (const float*)d_in[8];
    const float* ln2_g  = (const float*)d_in[9];
    const float* ln2_b  = (const float*)d_in[10];
    const float* W1     = (const float*)d_in[11];
    const float* b1     = (const float*)d_in[12];
    const float* W2     = (const float*)d_in[13];
    const float* b2     = (const float*)d_in[14];
    float* out = (float*)d_out;

    float *gx, *gtmp;
    __half *gxh, *gah, *ghh, *gwh, *gwl, *gqh, *gql, *gvh, *gvl;
    cudaGetSymbolAddress((void**)&gx,   g_x);
    cudaGetSymbolAddress((void**)&gtmp, g_tmp);
    cudaGetSymbolAddress((void**)&gxh,  g_xh);
    cudaGetSymbolAddress((void**)&gah,  g_ah);
    cudaGetSymbolAddress((void**)&ghh,  g_hh);
    cudaGetSymbolAddress((void**)&gwh,  g_wh);  cudaGetSymbolAddress((void**)&gwl, g_wl);
    cudaGetSymbolAddress((void**)&gqh,  g_qkvh); cudaGetSymbolAddress((void**)&gql, g_qkvl);
    cudaGetSymbolAddress((void**)&gvh,  g_vh);  cudaGetSymbolAddress((void**)&gvl, g_vl);

    cudaFuncSetAttribute(gemm_hmma2<0>, cudaFuncAttributeMaxDynamicSharedMemorySize, GEMM_SMEM_BYTES);
    cudaFuncSetAttribute(gemm_hmma2<1>, cudaFuncAttributeMaxDynamicSharedMemorySize, GEMM_SMEM_BYTES);
    cudaFuncSetAttribute(gemm_hmma2<2>, cudaFuncAttributeMaxDynamicSharedMemorySize, GEMM_SMEM_BYTES);
    cudaFuncSetAttribute(attn_mma_kernel, cudaFuncAttributeMaxDynamicSharedMemorySize, ATTN_SMEM);

    const int CONV_BLK = 592;

    embed_ln_kernel<<<NROWS, 256>>>(x, norm_g, norm_b, gx, gxh);

    for (int l = 0; l < N_LAYERS; l++) {
        const size_t oQ = (size_t)l * 3 * C_DIM * C_DIM;
        const size_t oO = (size_t)l * C_DIM * C_DIM;
        const size_t o1 = (size_t)l * HID_DIM * C_DIM;
        const size_t o2 = (size_t)l * C_DIM * HID_DIM;
        const float* bqkv_l = bqkv + (size_t)l * 3 * C_DIM;

        // split QKV weights, then Wo weights (dedicated buffer) -> gemmQKV is launch #4
        split_f32_kernel<<<CONV_BLK, 256>>>(Wqkv + oQ, gwh, gwl, 3 * C_DIM * C_DIM);
        split_f32_kernel<<<CONV_BLK, 256>>>(Wo + oO, gvh, gvl, C_DIM * C_DIM);

        // qkv = (x @ Wqkv^T + bqkv), Q scaled by 1/8, fp16 hi+lo out
        gemm_hmma2<2><<<dim3(3 * C_DIM / 128, NROWS / 128), 256, GEMM_SMEM_BYTES>>>(
            gxh, gwh, gwl, bqkv_l, nullptr, gqh, gql,
            NROWS, 3 * C_DIM, C_DIM);

        // fp16 HMMA flash attention -> fp16 hi
        attn_mma_kernel<<<dim3(SEQ / 64, N_HEADS, BATCH), 128, ATTN_SMEM>>>(
            gqh, gql, bqkv_l, gah);

        // o = attn @ Wo^T + bo
        gemm_hmma2<0><<<dim3(C_DIM / 128, NROWS / 128), 256, GEMM_SMEM_BYTES>>>(
            gah, gvh, gvl, bo + (size_t)l * C_DIM, gtmp, nullptr, nullptr,
            NROWS, C_DIM, C_DIM);

        // x = LN(x + o; ln1)
        add_ln_kernel<1><<<NROWS, 256>>>(gx, gtmp, ln1_g + l * C_DIM, ln1_b + l * C_DIM, gx, gxh);

        // hid = gelu(x @ W1^T + b1) -> fp16 hi
        split_f32_kernel<<<CONV_BLK, 256>>>(W1 + o1, gwh, gwl, HID_DIM * C_DIM);
        gemm_hmma2<1><<<dim3(HID_DIM / 128, NROWS / 128), 256, GEMM_SMEM_BYTES>>>(
            gxh, gwh, gwl, b1 + (size_t)l * HID_DIM, nullptr, ghh, nullptr,
            NROWS, HID_DIM, C_DIM);

        // ff = hid @ W2^T + b2
        split_f32_kernel<<<CONV_BLK, 256>>>(W2 + o2, gwh, gwl, C_DIM * HID_DIM);
        gemm_hmma2<0><<<dim3(C_DIM / 128, NROWS / 128), 256, GEMM_SMEM_BYTES>>>(
            ghh, gwh, gwl, b2 + (size_t)l * C_DIM, gtmp, nullptr, nullptr,
            NROWS, C_DIM, HID_DIM);

        // x = LN(x + ff; ln2)
        if (l == N_LAYERS - 1)
            add_ln_kernel<0><<<NROWS, 256>>>(gx, gtmp, ln2_g + l * C_DIM, ln2_b + l * C_DIM, out, nullptr);
        else
            add_ln_kernel<1><<<NROWS, 256>>>(gx, gtmp, ln2_g + l * C_DIM, ln2_b + l * C_DIM, gx, gxh);
    }
}

// round 12
// speedup vs baseline: 1.6105x; 1.0823x over previous
#include <cuda_runtime.h>
#include <cuda_fp16.h>
#include <math.h>
#include <stdint.h>

#define C_DIM   1024
#define N_HEADS 16
#define HD      64
#define N_LAYERS 6
#define HID_DIM 4096
#define BATCH   2
#define SEQ     2048
#define NROWS   (BATCH*SEQ)
#define WIN     1000

// ================= scratch (no allocations allowed) =================
__device__ float g_x   [NROWS * C_DIM];
__device__ float g_tmp [NROWS * C_DIM];
__device__ __half g_xh[NROWS * C_DIM];
__device__ __half g_ah[NROWS * C_DIM];
__device__ __half g_hh[NROWS * HID_DIM];
__device__ __half g_qkvh[NROWS * 3 * C_DIM];
// per-layer split weight staging (reused; max 4M elems) + dedicated Wo staging
#define WMAX (HID_DIM * C_DIM)
__device__ __half g_wh[WMAX], g_wl[WMAX];
__device__ __half g_vh[C_DIM * C_DIM], g_vl[C_DIM * C_DIM];

// ================= helpers =================
__device__ __forceinline__ uint32_t smem_to_u32(const void* p) {
    uint32_t a;
    asm("{ .reg .u64 t; cvta.to.shared.u64 t, %1; cvt.u32.u64 %0, t; }" : "=r"(a) : "l"(p));
    return a;
}

__device__ __forceinline__ void ldsm4(uint32_t* r, uint32_t addr) {
    asm volatile("ldmatrix.sync.aligned.m8n8.x4.shared.b16 {%0,%1,%2,%3}, [%4];"
                 : "=r"(r[0]), "=r"(r[1]), "=r"(r[2]), "=r"(r[3]) : "r"(addr));
}
__device__ __forceinline__ void ldsm4t(uint32_t* r, uint32_t addr) {
    asm volatile("ldmatrix.sync.aligned.m8n8.x4.trans.shared.b16 {%0,%1,%2,%3}, [%4];"
                 : "=r"(r[0]), "=r"(r[1]), "=r"(r[2]), "=r"(r[3]) : "r"(addr));
}
__device__ __forceinline__ void mma16816(float* d, const uint32_t* a, uint32_t b0, uint32_t b1) {
    asm volatile("mma.sync.aligned.m16n8k16.row.col.f32.f16.f16.f32 "
                 "{%0,%1,%2,%3}, {%4,%5,%6,%7}, {%8,%9}, {%0,%1,%2,%3};"
                 : "+f"(d[0]), "+f"(d[1]), "+f"(d[2]), "+f"(d[3])
                 : "r"(a[0]), "r"(a[1]), "r"(a[2]), "r"(a[3]), "r"(b0), "r"(b1));
}
__device__ __forceinline__ uint32_t packh(float lo, float hi) {
    uint32_t r;
    asm("cvt.rn.f16x2.f32 %0, %1, %2;" : "=r"(r) : "f"(hi), "f"(lo));
    return r;
}
__device__ __forceinline__ void split_pair(float v, __half& hi, __half& lo) {
    hi = __float2half_rn(v);
    lo = __float2half_rn(v - __half2float(hi));
}
#define CPA16(dst, src) \
    asm volatile("cp.async.cg.shared.global [%0], [%1], 16;" :: "r"(dst), "l"(src))

// ================= weight split kernel =================
__global__ void split_f32_kernel(const float* __restrict__ w, __half* __restrict__ h,
                                 __half* __restrict__ l, int n) {
    int i = blockIdx.x * blockDim.x + threadIdx.x;
    int stride = gridDim.x * blockDim.x;
    for (; i < n; i += stride) {
        float v = w[i];
        __half hi, lo;
        split_pair(v, hi, lo);
        h[i] = hi; l[i] = lo;
    }
}

// ================= block reduce =================
__device__ __forceinline__ float blk_sum(float v, float* sh) {
    int tid = threadIdx.x;
    sh[tid] = v; __syncthreads();
#pragma unroll
    for (int s = 128; s > 0; s >>= 1) { if (tid < s) sh[tid] += sh[tid + s]; __syncthreads(); }
    float r = sh[0]; __syncthreads();
    return r;
}

// ================= input LN + positional embedding =================
__global__ __launch_bounds__(256) void embed_ln_kernel(
    const float* __restrict__ x, const float* __restrict__ g, const float* __restrict__ b,
    float* __restrict__ out, __half* __restrict__ oh)
{
    __shared__ float sh[256];
    int r = blockIdx.x, t = r % SEQ, tid = threadIdx.x;
    const float* xr = x + (size_t)r * C_DIM;
    float v[4]; float s = 0.f;
#pragma unroll
    for (int i = 0; i < 4; i++) { v[i] = xr[tid + 256 * i]; s += v[i]; }
    float mean = blk_sum(s, sh) * (1.0f / C_DIM);
    float d2 = 0.f;
#pragma unroll
    for (int i = 0; i < 4; i++) { float d = v[i] - mean; d2 += d * d; }
    float inv = rsqrtf(blk_sum(d2, sh) * (1.0f / C_DIM) + 1e-5f);
    const float kln = 9.2103403719761836f / 511.0f;
    float tf = (float)t;
#pragma unroll
    for (int i = 0; i < 4; i++) {
        int c = tid + 256 * i;
        float ph = (c < 512) ? tf * expf(-((float)c) * kln) : tf * expf(-((float)(c - 512)) * kln);
        float pos = (c < 512) ? cosf(ph) : sinf(ph);
        float y = (v[i] - mean) * inv * g[c] + b[c] + pos;
        size_t idx = (size_t)r * C_DIM + c;
        out[idx] = y;
        oh[idx] = __float2half_rn(y);
    }
}

// ================= y = LN(xin+add) =================
template<int SPLIT>
__global__ __launch_bounds__(256) void add_ln_kernel(
    const float* __restrict__ xin, const float* __restrict__ add,
    const float* __restrict__ g, const float* __restrict__ b,
    float* __restrict__ out, __half* __restrict__ oh)
{
    __shared__ float sh[256];
    int r = blockIdx.x, tid = threadIdx.x;
    const float* xr = xin + (size_t)r * C_DIM;
    const float* ar = add + (size_t)r * C_DIM;
    float v[4]; float s = 0.f;
#pragma unroll
    for (int i = 0; i < 4; i++) { int c = tid + 256 * i; v[i] = xr[c] + ar[c]; s += v[i]; }
    float mean = blk_sum(s, sh) * (1.0f / C_DIM);
    float d2 = 0.f;
#pragma unroll
    for (int i = 0; i < 4; i++) { float d = v[i] - mean; d2 += d * d; }
    float inv = rsqrtf(blk_sum(d2, sh) * (1.0f / C_DIM) + 1e-5f);
#pragma unroll
    for (int i = 0; i < 4; i++) {
        int c = tid + 256 * i;
        float y = (v[i] - mean) * inv * g[c] + b[c];
        size_t idx = (size_t)r * C_DIM + c;
        out[idx] = y;
        if (SPLIT) oh[idx] = __float2half_rn(y);
    }
}

// ================= fp16 2-pass HMMA GEMM ===================
// C[M,N] = Ah[M,K] * (Bh+Bl)[N,K]^T + bias   (A-side lo dropped: 2^-11 residual)
// CTA tile 128x128, 256 thr (8 warps 2Mx4N, warp 64x32), BK=64, 2-stage cp.async,
// 2 CTAs/SM. Stage = Ah(16K) | Bh(16K) | Bl(16K) = 48KB.
// OUT_MODE 0: fp32 + bias. 1: gelu(.)->fp16. 2: (.)*qscale->fp16 (QKV).
#define GEMM_SMEM_BYTES (1024 + 2 * 49152)

template<int OUT_MODE>
__global__ __launch_bounds__(256, 2) void gemm_hmma2(
    const __half* __restrict__ Ah,
    const __half* __restrict__ Bh, const __half* __restrict__ Bl,
    const float* __restrict__ bias,
    float* __restrict__ Cf, __half* __restrict__ Ch,
    int M, int N, int K)
{
    extern __shared__ char dsm[];
    const uint32_t tiles = (smem_to_u32(dsm) + 1023u) & ~1023u;
    const int tid = threadIdx.x;
    const int wid = tid >> 5;
    const int lid = tid & 31;
    const int warp_m = wid & 1;        // 2 M-warps * 64 rows
    const int warp_n = wid >> 1;       // 4 N-warps * 32 cols
    const int row0 = blockIdx.y * 128;
    const int col0 = blockIdx.x * 128;
    const int nchunk = K >> 6;

    const char* gsrc[3] = {
        (const char*)(Ah + (size_t)row0 * K),
        (const char*)(Bh + (size_t)col0 * K),
        (const char*)(Bl + (size_t)col0 * K) };
    const size_t rowbytes = (size_t)K * 2;

    // branch-free: tile t compile-time, 4 sub-iterations each (1024 16B units/tile)
    auto load_chunk = [&](int c, int st) {
        const uint32_t sb = tiles + st * 49152;
        const size_t koff = (size_t)c * 128;
#pragma unroll
        for (int t = 0; t < 3; t++) {
#pragma unroll
            for (int j = 0; j < 4; j++) {
                int u = tid + j * 256;             // 0..1023
                int r = u >> 3;
                int cb = (u & 7) * 16;
                const char* g = gsrc[t] + (size_t)r * rowbytes + koff + cb;
                uint32_t sa = sb + t * 16384 + (uint32_t)(r * 128 + (cb ^ ((r & 7) << 4)));
                CPA16(sa, g);
            }
        }
        asm volatile("cp.async.commit_group;");
    };

    float acc[4][4][4];
#pragma unroll
    for (int a = 0; a < 4; a++)
#pragma unroll
        for (int b = 0; b < 4; b++)
#pragma unroll
            for (int i = 0; i < 4; i++) acc[a][b][i] = 0.f;

    const int lane15 = lid & 15;
    const int lanehi = lid >> 4;
    const int xr = lane15 & 7;

    load_chunk(0, 0);

    for (int c = 0; c < nchunk; c++) {
        const int st = c & 1;
        if (c + 1 < nchunk) {
            load_chunk(c + 1, st ^ 1);
            asm volatile("cp.async.wait_group 1;");
        } else {
            asm volatile("cp.async.wait_group 0;");
        }
        __syncthreads();

        const uint32_t sb = tiles + st * 49152;
        const uint32_t aBase  = sb          + (uint32_t)(warp_m * 64 + lane15) * 128;
        const uint32_t bBaseH = sb + 16384  + (uint32_t)(warp_n * 32 + lane15) * 128;
        const uint32_t bBaseL = sb + 32768  + (uint32_t)(warp_n * 32 + lane15) * 128;

#pragma unroll
        for (int ks = 0; ks < 4; ks++) {
            const uint32_t uoff = (uint32_t)(((ks * 2 + lanehi) ^ xr) * 16);
            uint32_t ah[4][4], bhv[2][4], blv[2][4];
#pragma unroll
            for (int mt = 0; mt < 4; mt++)
                ldsm4(ah[mt], aBase + mt * 2048 + uoff);
#pragma unroll
            for (int pt = 0; pt < 2; pt++) {
                ldsm4(bhv[pt], bBaseH + pt * 2048 + uoff);
                ldsm4(blv[pt], bBaseL + pt * 2048 + uoff);
            }
#pragma unroll
            for (int mt = 0; mt < 4; mt++) {
#pragma unroll
                for (int nt = 0; nt < 4; nt++) {
                    const int pt = nt >> 1, o = nt & 1;
                    mma16816(acc[mt][nt], ah[mt], bhv[pt][o], bhv[pt][o + 2]);
                    mma16816(acc[mt][nt], ah[mt], blv[pt][o], blv[pt][o + 2]);
                }
            }
        }
        __syncthreads();
    }

    const int lr = lid >> 2;
    const int lc = (lid & 3) * 2;
#pragma unroll
    for (int mt = 0; mt < 4; mt++) {
        const int row = row0 + warp_m * 64 + mt * 16 + lr;
#pragma unroll
        for (int nt = 0; nt < 4; nt++) {
            const int col = col0 + warp_n * 32 + nt * 8 + lc;
            const float b0 = bias[col], b1 = bias[col + 1];
            float v0 = acc[mt][nt][0] + b0, v1 = acc[mt][nt][1] + b1;
            float v2 = acc[mt][nt][2] + b0, v3 = acc[mt][nt][3] + b1;
            if (OUT_MODE == 0) {
                float2 w0; w0.x = v0; w0.y = v1;
                float2 w1; w1.x = v2; w1.y = v3;
                *(float2*)(Cf + (size_t)row * N + col) = w0;
                *(float2*)(Cf + (size_t)(row + 8) * N + col) = w1;
            } else {
                if (OUT_MODE == 1) {
                    v0 = 0.5f * v0 * (1.f + erff(v0 * 0.70710678118654752f));
                    v1 = 0.5f * v1 * (1.f + erff(v1 * 0.70710678118654752f));
                    v2 = 0.5f * v2 * (1.f + erff(v2 * 0.70710678118654752f));
                    v3 = 0.5f * v3 * (1.f + erff(v3 * 0.70710678118654752f));
                } else {
                    float sc = (col < C_DIM) ? 0.125f : 1.0f;  // scale Q only
                    v0 *= sc; v1 *= sc; v2 *= sc; v3 *= sc;
                }
                __half2 hh0 = __floats2half2_rn(v0, v1);
                __half2 hh1 = __floats2half2_rn(v2, v3);
                *(__half2*)(Ch + (size_t)row * N + col) = hh0;
                *(__half2*)(Ch + (size_t)(row + 8) * N + col) = hh1;
            }
        }
    }
}

// ================= fp16 HMMA flash attention (sliding window) ===================
// Pure fp16: S = Q*K^T (1 pass), P fp16, O += P*V (1 pass).
#define ATTN_SMEM (1024 + 3 * 8192)

__global__ __launch_bounds__(128, 4) void attn_mma_kernel(
    const __half* __restrict__ qkvh,
    const float* __restrict__ bqkv_l,
    __half* __restrict__ oh)
{
    extern __shared__ char dsm[];
    const uint32_t base = (smem_to_u32(dsm) + 1023u) & ~1023u;
    const uint32_t sQ = base;
    const uint32_t sK = base + 8192;
    const uint32_t sV = base + 16384;

    const int tid = threadIdx.x, wid = tid >> 5, lid = tid & 31;
    const int b = blockIdx.z, h = blockIdx.y, q0 = blockIdx.x * 64;
    const int lane15 = lid & 15, lanehi = lid >> 4, xr = lane15 & 7;
    const int tig = lid & 3, gid = lid >> 2;
    const size_t RS = 3 * C_DIM;

    // ---- Q tile: 64 rows x 128B ----
#pragma unroll
    for (int i = 0; i < 4; i++) {
        int u = tid + i * 128;          // 0..511
        int r = u >> 3, cu = u & 7;
        const char* g = (const char*)(qkvh + (size_t)(b * SEQ + q0 + r) * RS + h * HD) + cu * 16;
        CPA16(sQ + (uint32_t)(r * 128 + ((cu ^ (r & 7)) * 16)), g);
    }
    asm volatile("cp.async.commit_group;");
    asm volatile("cp.async.wait_group 0;");
    __syncthreads();

    uint32_t qf[4][4];
    {
        const uint32_t qrb = (uint32_t)((wid * 16 + lane15) * 128);
#pragma unroll
        for (int ks = 0; ks < 4; ks++) {
            const uint32_t uoff = (uint32_t)(((ks * 2 + lanehi) ^ xr) * 16);
            ldsm4(qf[ks], sQ + qrb + uoff);
        }
    }

    // ---- past zero-token init ----
    const int tq0 = q0 + wid * 16 + gid, tq1 = tq0 + 8;
    const float* bk = bqkv_l + C_DIM + h * HD;
    const float* bv = bqkv_l + 2 * C_DIM + h * HD;
    float sp0 = 0.f, sp1 = 0.f;
    {
        const __half* q0p = qkvh + (size_t)(b * SEQ + tq0) * RS + h * HD + tig * 16;
        const __half* q1p = qkvh + (size_t)(b * SEQ + tq1) * RS + h * HD + tig * 16;
#pragma unroll
        for (int dd = 0; dd < 16; dd++) {
            float w = bk[tig * 16 + dd];
            sp0 += __half2float(q0p[dd]) * w;
            sp1 += __half2float(q1p[dd]) * w;
        }
        sp0 += __shfl_xor_sync(0xFFFFFFFF, sp0, 1); sp0 += __shfl_xor_sync(0xFFFFFFFF, sp0, 2);
        sp1 += __shfl_xor_sync(0xFFFFFFFF, sp1, 1); sp1 += __shfl_xor_sync(0xFFFFFFFF, sp1, 2);
    }
    const bool pv0 = (tq0 <= WIN - 1), pv1 = (tq1 <= WIN - 1);
    float m0 = pv0 ? sp0 : -1e30f, m1 = pv1 ? sp1 : -1e30f;
    float l0 = pv0 ? 1.f : 0.f,     l1 = pv1 ? 1.f : 0.f;
    float o[8][4];
#pragma unroll
    for (int nt = 0; nt < 8; nt++) {
        float bva = bv[nt * 8 + 2 * tig], bvb = bv[nt * 8 + 2 * tig + 1];
        o[nt][0] = pv0 ? bva : 0.f; o[nt][1] = pv0 ? bvb : 0.f;
        o[nt][2] = pv1 ? bva : 0.f; o[nt][3] = pv1 ? bvb : 0.f;
    }

    // ---- main loop over 64-key tiles ----
    const int jlo = (q0 > WIN) ? ((q0 - WIN) & ~63) : 0;
    for (int j0 = jlo; j0 < q0 + 64; j0 += 64) {
        __syncthreads();
#pragma unroll
        for (int i = 0; i < 8; i++) {
            int u = tid + i * 128;       // 0..1023
            int t = u >> 9, idx = u & 511;
            int r = idx >> 3, cu = idx & 7;
            const size_t coloff = (size_t)C_DIM * (1 + t) + h * HD;
            const char* g = (const char*)(qkvh + (size_t)(b * SEQ + j0 + r) * RS + coloff) + cu * 16;
            CPA16(sK + (uint32_t)(t * 8192 + r * 128 + ((cu ^ (r & 7)) * 16)), g);
        }
        asm volatile("cp.async.commit_group;");
        asm volatile("cp.async.wait_group 0;");
        __syncthreads();

        // S = Q.K^T (1 pass)
        float s[8][4];
#pragma unroll
        for (int nt = 0; nt < 8; nt++)
#pragma unroll
            for (int i = 0; i < 4; i++) s[nt][i] = 0.f;
#pragma unroll
        for (int ks = 0; ks < 4; ks++) {
            const uint32_t uoff = (uint32_t)(((ks * 2 + lanehi) ^ xr) * 16);
            uint32_t kf[4][4];
#pragma unroll
            for (int pt = 0; pt < 4; pt++)
                ldsm4(kf[pt], sK + (uint32_t)((pt * 16 + lane15) * 128) + uoff);
#pragma unroll
            for (int nt = 0; nt < 8; nt++) {
                const int pt = nt >> 1, oo = nt & 1;
                mma16816(s[nt], qf[ks], kf[pt][oo], kf[pt][oo + 2]);
            }
        }
        // mask
#pragma unroll
        for (int nt = 0; nt < 8; nt++)
#pragma unroll
            for (int i = 0; i < 4; i++) {
                int key = j0 + nt * 8 + 2 * tig + (i & 1);
                int tq = (i < 2) ? tq0 : tq1;
                int dlt = tq - key;
                if (dlt < 0 || dlt > WIN) s[nt][i] = -3.0e38f;
            }
        // online softmax
        float mc0 = -3.0e38f, mc1 = -3.0e38f;
#pragma unroll
        for (int nt = 0; nt < 8; nt++) {
            mc0 = fmaxf(mc0, fmaxf(s[nt][0], s[nt][1]));
            mc1 = fmaxf(mc1, fmaxf(s[nt][2], s[nt][3]));
        }
        mc0 = fmaxf(mc0, __shfl_xor_sync(0xFFFFFFFF, mc0, 1));
        mc0 = fmaxf(mc0, __shfl_xor_sync(0xFFFFFFFF, mc0, 2));
        mc1 = fmaxf(mc1, __shfl_xor_sync(0xFFFFFFFF, mc1, 1));
        mc1 = fmaxf(mc1, __shfl_xor_sync(0xFFFFFFFF, mc1, 2));
        float mn0 = fmaxf(m0, mc0), mn1 = fmaxf(m1, mc1);
        float a0 = __expf(m0 - mn0), a1 = __expf(m1 - mn1);
        float rs0 = 0.f, rs1 = 0.f;
#pragma unroll
        for (int nt = 0; nt < 8; nt++) {
            s[nt][0] = __expf(s[nt][0] - mn0); rs0 += s[nt][0];
            s[nt][1] = __expf(s[nt][1] - mn0); rs0 += s[nt][1];
            s[nt][2] = __expf(s[nt][2] - mn1); rs1 += s[nt][2];
            s[nt][3] = __expf(s[nt][3] - mn1); rs1 += s[nt][3];
        }
        rs0 += __shfl_xor_sync(0xFFFFFFFF, rs0, 1); rs0 += __shfl_xor_sync(0xFFFFFFFF, rs0, 2);
        rs1 += __shfl_xor_sync(0xFFFFFFFF, rs1, 1); rs1 += __shfl_xor_sync(0xFFFFFFFF, rs1, 2);
        l0 = l0 * a0 + rs0; l1 = l1 * a1 + rs1;
        m0 = mn0; m1 = mn1;
#pragma unroll
        for (int nt = 0; nt < 8; nt++) {
            o[nt][0] *= a0; o[nt][1] *= a0; o[nt][2] *= a1; o[nt][3] *= a1;
        }
        // pack P -> fp16 A-frags
        uint32_t pa[4][4];
#pragma unroll
        for (int kt = 0; kt < 4; kt++) {
            pa[kt][0] = packh(s[2 * kt][0],     s[2 * kt][1]);
            pa[kt][1] = packh(s[2 * kt][2],     s[2 * kt][3]);
            pa[kt][2] = packh(s[2 * kt + 1][0], s[2 * kt + 1][1]);
            pa[kt][3] = packh(s[2 * kt + 1][2], s[2 * kt + 1][3]);
        }
        // O += P * V (1 pass)
#pragma unroll
        for (int kt = 0; kt < 4; kt++) {
            const uint32_t vrb = (uint32_t)((kt * 16 + lane15) * 128);
            uint32_t vf[4][4];
#pragma unroll
            for (int j = 0; j < 4; j++) {
                const uint32_t uo = (uint32_t)(((j * 2 + lanehi) ^ xr) * 16);
                ldsm4t(vf[j], sV + vrb + uo);
            }
#pragma unroll
            for (int j = 0; j < 4; j++) {
                mma16816(o[2 * j],     pa[kt], vf[j][0], vf[j][1]);
                mma16816(o[2 * j + 1], pa[kt], vf[j][2], vf[j][3]);
            }
        }
    }

    const float r0 = 1.f / l0, r1 = 1.f / l1;
#pragma unroll
    for (int nt = 0; nt < 8; nt++) {
        const int col = h * HD + nt * 8 + 2 * tig;
        __half2 hh0 = __floats2half2_rn(o[nt][0] * r0, o[nt][1] * r0);
        __half2 hh1 = __floats2half2_rn(o[nt][2] * r1, o[nt][3] * r1);
        *(__half2*)(oh + (size_t)(b * SEQ + tq0) * C_DIM + col) = hh0;
        *(__half2*)(oh + (size_t)(b * SEQ + tq1) * C_DIM + col) = hh1;
    }
}

// ================= launcher =================
extern "C" void kernel_launch(void* const* d_in, const int* in_sizes, int n_in,
                              void* d_out, int out_size)
{
    const float* x      = (const float*)d_in[0];
    const float* norm_g = (const float*)d_in[1];
    const float* norm_b = (const float*)d_in[2];
    const float* Wqkv   = (const float*)d_in[3];
    const float* bqkv   = (const float*)d_in[4];
    const float* Wo     = (const float*)d_in[5];
    const float* bo     = (const float*)d_in[6];
    const float* ln1_g  = (const float*)d_in[7];
    const float* ln1_b  = (const float*)d_in[8];
    const float* ln2_g  = (const float*)d_in[9];
    const float* ln2_b  = (const float*)d_in[10];
    const float* W1     = (const float*)d_in[11];
    const float* b1     = (const float*)d_in[12];
    const float* W2     = (const float*)d_in[13];
    const float* b2     = (const float*)d_in[14];
    float* out = (float*)d_out;

    float *gx, *gtmp;
    __half *gxh, *gah, *ghh, *gwh, *gwl, *gqh, *gvh, *gvl;
    cudaGetSymbolAddress((void**)&gx,   g_x);
    cudaGetSymbolAddress((void**)&gtmp, g_tmp);
    cudaGetSymbolAddress((void**)&gxh,  g_xh);
    cudaGetSymbolAddress((void**)&gah,  g_ah);
    cudaGetSymbolAddress((void**)&ghh,  g_hh);
    cudaGetSymbolAddress((void**)&gwh,  g_wh);  cudaGetSymbolAddress((void**)&gwl, g_wl);
    cudaGetSymbolAddress((void**)&gqh,  g_qkvh);
    cudaGetSymbolAddress((void**)&gvh,  g_vh);  cudaGetSymbolAddress((void**)&gvl, g_vl);

    cudaFuncSetAttribute(gemm_hmma2<0>, cudaFuncAttributeMaxDynamicSharedMemorySize, GEMM_SMEM_BYTES);
    cudaFuncSetAttribute(gemm_hmma2<1>, cudaFuncAttributeMaxDynamicSharedMemorySize, GEMM_SMEM_BYTES);
    cudaFuncSetAttribute(gemm_hmma2<2>, cudaFuncAttributeMaxDynamicSharedMemorySize, GEMM_SMEM_BYTES);
    cudaFuncSetAttribute(attn_mma_kernel, cudaFuncAttributeMaxDynamicSharedMemorySize, ATTN_SMEM);

    const int CONV_BLK = 592;

    embed_ln_kernel<<<NROWS, 256>>>(x, norm_g, norm_b, gx, gxh);

    for (int l = 0; l < N_LAYERS; l++) {
        const size_t oQ = (size_t)l * 3 * C_DIM * C_DIM;
        const size_t oO = (size_t)l * C_DIM * C_DIM;
        const size_t o1 = (size_t)l * HID_DIM * C_DIM;
        const size_t o2 = (size_t)l * C_DIM * HID_DIM;
        const float* bqkv_l = bqkv + (size_t)l * 3 * C_DIM;

        // split QKV weights, then Wo weights (dedicated buffer) -> gemmQKV is launch #4
        split_f32_kernel<<<CONV_BLK, 256>>>(Wqkv + oQ, gwh, gwl, 3 * C_DIM * C_DIM);
        split_f32_kernel<<<CONV_BLK, 256>>>(Wo + oO, gvh, gvl, C_DIM * C_DIM);

        // qkv = (x @ Wqkv^T + bqkv), Q scaled by 1/8, fp16 out
        gemm_hmma2<2><<<dim3(3 * C_DIM / 128, NROWS / 128), 256, GEMM_SMEM_BYTES>>>(
            gxh, gwh, gwl, bqkv_l, nullptr, gqh,
            NROWS, 3 * C_DIM, C_DIM);

        // pure-fp16 HMMA flash attention
        attn_mma_kernel<<<dim3(SEQ / 64, N_HEADS, BATCH), 128, ATTN_SMEM>>>(
            gqh, bqkv_l, gah);

        // o = attn @ Wo^T + bo
        gemm_hmma2<0><<<dim3(C_DIM / 128, NROWS / 128), 256, GEMM_SMEM_BYTES>>>(
            gah, gvh, gvl, bo + (size_t)l * C_DIM, gtmp, nullptr,
            NROWS, C_DIM, C_DIM);

        // x = LN(x + o; ln1)
        add_ln_kernel<1><<<NROWS, 256>>>(gx, gtmp, ln1_g + l * C_DIM, ln1_b + l * C_DIM, gx, gxh);

        // hid = gelu(x @ W1^T + b1) -> fp16
        split_f32_kernel<<<CONV_BLK, 256>>>(W1 + o1, gwh, gwl, HID_DIM * C_DIM);
        gemm_hmma2<1><<<dim3(HID_DIM / 128, NROWS / 128), 256, GEMM_SMEM_BYTES>>>(
            gxh, gwh, gwl, b1 + (size_t)l * HID_DIM, nullptr, ghh,
            NROWS, HID_DIM, C_DIM);

        // ff = hid @ W2^T + b2
        split_f32_kernel<<<CONV_BLK, 256>>>(W2 + o2, gwh, gwl, C_DIM * HID_DIM);
        gemm_hmma2<0><<<dim3(C_DIM / 128, NROWS / 128), 256, GEMM_SMEM_BYTES>>>(
            ghh, gwh, gwl, b2 + (size_t)l * C_DIM, gtmp, nullptr,
            NROWS, C_DIM, HID_DIM);

        // x = LN(x + ff; ln2)
        if (l == N_LAYERS - 1)
            add_ln_kernel<0><<<NROWS, 256>>>(gx, gtmp, ln2_g + l * C_DIM, ln2_b + l * C_DIM, out, nullptr);
        else
            add_ln_kernel<1><<<NROWS, 256>>>(gx, gtmp, ln2_g + l * C_DIM, ln2_b + l * C_DIM, gx, gxh);
    }
}

// round 13
// speedup vs baseline: 2.5179x; 1.5635x over previous
#include <cuda_runtime.h>
#include <cuda_fp16.h>
#include <math.h>
#include <stdint.h>

#define C_DIM   1024
#define N_HEADS 16
#define HD      64
#define N_LAYERS 6
#define HID_DIM 4096
#define BATCH   2
#define SEQ     2048
#define NROWS   (BATCH*SEQ)
#define WIN     1000

// ================= scratch (no allocations allowed) =================
__device__ float g_x   [NROWS * C_DIM];
__device__ float g_tmp [NROWS * C_DIM];
__device__ __half g_xh[NROWS * C_DIM];
__device__ __half g_ah[NROWS * C_DIM];
__device__ __half g_hh[NROWS * HID_DIM];
__device__ __half g_qkvh[NROWS * 3 * C_DIM];
// per-layer fp16 weight staging (reused; max 4M elems) + dedicated Wo staging
#define WMAX (HID_DIM * C_DIM)
__device__ __half g_wh[WMAX];
__device__ __half g_vh[C_DIM * C_DIM];

// ================= helpers =================
__device__ __forceinline__ uint32_t smem_to_u32(const void* p) {
    uint32_t a;
    asm("{ .reg .u64 t; cvta.to.shared.u64 t, %1; cvt.u32.u64 %0, t; }" : "=r"(a) : "l"(p));
    return a;
}

__device__ __forceinline__ void ldsm4(uint32_t* r, uint32_t addr) {
    asm volatile("ldmatrix.sync.aligned.m8n8.x4.shared.b16 {%0,%1,%2,%3}, [%4];"
                 : "=r"(r[0]), "=r"(r[1]), "=r"(r[2]), "=r"(r[3]) : "r"(addr));
}
__device__ __forceinline__ void ldsm4t(uint32_t* r, uint32_t addr) {
    asm volatile("ldmatrix.sync.aligned.m8n8.x4.trans.shared.b16 {%0,%1,%2,%3}, [%4];"
                 : "=r"(r[0]), "=r"(r[1]), "=r"(r[2]), "=r"(r[3]) : "r"(addr));
}
__device__ __forceinline__ void mma16816(float* d, const uint32_t* a, uint32_t b0, uint32_t b1) {
    asm volatile("mma.sync.aligned.m16n8k16.row.col.f32.f16.f16.f32 "
                 "{%0,%1,%2,%3}, {%4,%5,%6,%7}, {%8,%9}, {%0,%1,%2,%3};"
                 : "+f"(d[0]), "+f"(d[1]), "+f"(d[2]), "+f"(d[3])
                 : "r"(a[0]), "r"(a[1]), "r"(a[2]), "r"(a[3]), "r"(b0), "r"(b1));
}
__device__ __forceinline__ uint32_t packh(float lo, float hi) {
    uint32_t r;
    asm("cvt.rn.f16x2.f32 %0, %1, %2;" : "=r"(r) : "f"(hi), "f"(lo));
    return r;
}
#define CPA16(dst, src) \
    asm volatile("cp.async.cg.shared.global [%0], [%1], 16;" :: "r"(dst), "l"(src))

// ================= weight cast kernel (fp32 -> fp16) =================
__global__ void cast_f16_kernel(const float* __restrict__ w, __half* __restrict__ h, int n) {
    int i = blockIdx.x * blockDim.x + threadIdx.x;
    int stride = gridDim.x * blockDim.x;
    for (int j = i * 2; j < n; j += stride * 2) {
        float2 v = *(const float2*)(w + j);
        *(__half2*)(h + j) = __floats2half2_rn(v.x, v.y);
    }
}

// ================= block reduce =================
__device__ __forceinline__ float blk_sum(float v, float* sh) {
    int tid = threadIdx.x;
    sh[tid] = v; __syncthreads();
#pragma unroll
    for (int s = 128; s > 0; s >>= 1) { if (tid < s) sh[tid] += sh[tid + s]; __syncthreads(); }
    float r = sh[0]; __syncthreads();
    return r;
}

// ================= input LN + positional embedding =================
__global__ __launch_bounds__(256) void embed_ln_kernel(
    const float* __restrict__ x, const float* __restrict__ g, const float* __restrict__ b,
    float* __restrict__ out, __half* __restrict__ oh)
{
    __shared__ float sh[256];
    int r = blockIdx.x, t = r % SEQ, tid = threadIdx.x;
    const float* xr = x + (size_t)r * C_DIM;
    float v[4]; float s = 0.f;
#pragma unroll
    for (int i = 0; i < 4; i++) { v[i] = xr[tid + 256 * i]; s += v[i]; }
    float mean = blk_sum(s, sh) * (1.0f / C_DIM);
    float d2 = 0.f;
#pragma unroll
    for (int i = 0; i < 4; i++) { float d = v[i] - mean; d2 += d * d; }
    float inv = rsqrtf(blk_sum(d2, sh) * (1.0f / C_DIM) + 1e-5f);
    const float kln = 9.2103403719761836f / 511.0f;
    float tf = (float)t;
#pragma unroll
    for (int i = 0; i < 4; i++) {
        int c = tid + 256 * i;
        float ph = (c < 512) ? tf * expf(-((float)c) * kln) : tf * expf(-((float)(c - 512)) * kln);
        float pos = (c < 512) ? cosf(ph) : sinf(ph);
        float y = (v[i] - mean) * inv * g[c] + b[c] + pos;
        size_t idx = (size_t)r * C_DIM + c;
        out[idx] = y;
        oh[idx] = __float2half_rn(y);
    }
}

// ================= y = LN(xin+add) =================
template<int SPLIT>
__global__ __launch_bounds__(256) void add_ln_kernel(
    const float* __restrict__ xin, const float* __restrict__ add,
    const float* __restrict__ g, const float* __restrict__ b,
    float* __restrict__ out, __half* __restrict__ oh)
{
    __shared__ float sh[256];
    int r = blockIdx.x, tid = threadIdx.x;
    const float* xr = xin + (size_t)r * C_DIM;
    const float* ar = add + (size_t)r * C_DIM;
    float v[4]; float s = 0.f;
#pragma unroll
    for (int i = 0; i < 4; i++) { int c = tid + 256 * i; v[i] = xr[c] + ar[c]; s += v[i]; }
    float mean = blk_sum(s, sh) * (1.0f / C_DIM);
    float d2 = 0.f;
#pragma unroll
    for (int i = 0; i < 4; i++) { float d = v[i] - mean; d2 += d * d; }
    float inv = rsqrtf(blk_sum(d2, sh) * (1.0f / C_DIM) + 1e-5f);
#pragma unroll
    for (int i = 0; i < 4; i++) {
        int c = tid + 256 * i;
        float y = (v[i] - mean) * inv * g[c] + b[c];
        size_t idx = (size_t)r * C_DIM + c;
        out[idx] = y;
        if (SPLIT) oh[idx] = __float2half_rn(y);
    }
}

// ================= fp16 1-pass HMMA GEMM ===================
// C[M,N] = A[M,K] * B[N,K]^T + bias   (both fp16, fp32 accum)
// CTA tile 128x128, 256 thr (8 warps 2Mx4N, warp 64x32), BK=64,
// 3-stage cp.async (32KB/stage), 2 CTAs/SM.
// OUT_MODE 0: fp32 + bias. 1: gelu(.)->fp16. 2: (.)*qscale->fp16 (QKV).
#define GEMM_SMEM_BYTES (1024 + 3 * 32768)

template<int OUT_MODE>
__global__ __launch_bounds__(256, 2) void gemm_hmma1(
    const __half* __restrict__ Ah, const __half* __restrict__ Bh,
    const float* __restrict__ bias,
    float* __restrict__ Cf, __half* __restrict__ Ch,
    int M, int N, int K)
{
    extern __shared__ char dsm[];
    const uint32_t tiles = (smem_to_u32(dsm) + 1023u) & ~1023u;
    const int tid = threadIdx.x;
    const int wid = tid >> 5;
    const int lid = tid & 31;
    const int warp_m = wid & 1;        // 2 M-warps * 64 rows
    const int warp_n = wid >> 1;       // 4 N-warps * 32 cols
    const int row0 = blockIdx.y * 128;
    const int col0 = blockIdx.x * 128;
    const int nchunk = K >> 6;

    const char* gsrc[2] = {
        (const char*)(Ah + (size_t)row0 * K),
        (const char*)(Bh + (size_t)col0 * K) };
    const size_t rowbytes = (size_t)K * 2;

    auto load_chunk = [&](int c, int st) {
        const uint32_t sb = tiles + st * 32768;
        const size_t koff = (size_t)c * 128;
#pragma unroll
        for (int t = 0; t < 2; t++) {
#pragma unroll
            for (int j = 0; j < 4; j++) {
                int u = tid + j * 256;             // 0..1023
                int r = u >> 3;
                int cb = (u & 7) * 16;
                const char* g = gsrc[t] + (size_t)r * rowbytes + koff + cb;
                uint32_t sa = sb + t * 16384 + (uint32_t)(r * 128 + (cb ^ ((r & 7) << 4)));
                CPA16(sa, g);
            }
        }
        asm volatile("cp.async.commit_group;");
    };

    float acc[4][4][4];
#pragma unroll
    for (int a = 0; a < 4; a++)
#pragma unroll
        for (int b = 0; b < 4; b++)
#pragma unroll
            for (int i = 0; i < 4; i++) acc[a][b][i] = 0.f;

    const int lane15 = lid & 15;
    const int lanehi = lid >> 4;
    const int xr = lane15 & 7;

    load_chunk(0, 0);
    if (nchunk > 1) load_chunk(1, 1);

    for (int c = 0; c < nchunk; c++) {
        if (c + 1 < nchunk) {
            asm volatile("cp.async.wait_group 1;");
        } else {
            asm volatile("cp.async.wait_group 0;");
        }
        __syncthreads();
        if (c + 2 < nchunk) load_chunk(c + 2, (c + 2) % 3);

        const uint32_t sb = tiles + (c % 3) * 32768;
        const uint32_t aBase = sb          + (uint32_t)(warp_m * 64 + lane15) * 128;
        const uint32_t bBase = sb + 16384  + (uint32_t)(warp_n * 32 + lane15) * 128;

#pragma unroll
        for (int ks = 0; ks < 4; ks++) {
            const uint32_t uoff = (uint32_t)(((ks * 2 + lanehi) ^ xr) * 16);
            uint32_t ah[4][4], bhv[2][4];
#pragma unroll
            for (int mt = 0; mt < 4; mt++)
                ldsm4(ah[mt], aBase + mt * 2048 + uoff);
#pragma unroll
            for (int pt = 0; pt < 2; pt++)
                ldsm4(bhv[pt], bBase + pt * 2048 + uoff);
#pragma unroll
            for (int mt = 0; mt < 4; mt++) {
#pragma unroll
                for (int nt = 0; nt < 4; nt++) {
                    const int pt = nt >> 1, o = nt & 1;
                    mma16816(acc[mt][nt], ah[mt], bhv[pt][o], bhv[pt][o + 2]);
                }
            }
        }
        __syncthreads();
    }

    const int lr = lid >> 2;
    const int lc = (lid & 3) * 2;
#pragma unroll
    for (int mt = 0; mt < 4; mt++) {
        const int row = row0 + warp_m * 64 + mt * 16 + lr;
#pragma unroll
        for (int nt = 0; nt < 4; nt++) {
            const int col = col0 + warp_n * 32 + nt * 8 + lc;
            const float b0 = bias[col], b1 = bias[col + 1];
            float v0 = acc[mt][nt][0] + b0, v1 = acc[mt][nt][1] + b1;
            float v2 = acc[mt][nt][2] + b0, v3 = acc[mt][nt][3] + b1;
            if (OUT_MODE == 0) {
                float2 w0; w0.x = v0; w0.y = v1;
                float2 w1; w1.x = v2; w1.y = v3;
                *(float2*)(Cf + (size_t)row * N + col) = w0;
                *(float2*)(Cf + (size_t)(row + 8) * N + col) = w1;
            } else {
                if (OUT_MODE == 1) {
                    v0 = 0.5f * v0 * (1.f + erff(v0 * 0.70710678118654752f));
                    v1 = 0.5f * v1 * (1.f + erff(v1 * 0.70710678118654752f));
                    v2 = 0.5f * v2 * (1.f + erff(v2 * 0.70710678118654752f));
                    v3 = 0.5f * v3 * (1.f + erff(v3 * 0.70710678118654752f));
                } else {
                    float sc = (col < C_DIM) ? 0.125f : 1.0f;  // scale Q only
                    v0 *= sc; v1 *= sc; v2 *= sc; v3 *= sc;
                }
                __half2 hh0 = __floats2half2_rn(v0, v1);
                __half2 hh1 = __floats2half2_rn(v2, v3);
                *(__half2*)(Ch + (size_t)row * N + col) = hh0;
                *(__half2*)(Ch + (size_t)(row + 8) * N + col) = hh1;
            }
        }
    }
}

// ================= fp16 HMMA flash attention (sliding window) ===================
// Pure fp16: S = Q*K^T (1 pass), P fp16, O += P*V (1 pass).
#define ATTN_SMEM (1024 + 3 * 8192)

__global__ __launch_bounds__(128, 4) void attn_mma_kernel(
    const __half* __restrict__ qkvh,
    const float* __restrict__ bqkv_l,
    __half* __restrict__ oh)
{
    extern __shared__ char dsm[];
    const uint32_t base = (smem_to_u32(dsm) + 1023u) & ~1023u;
    const uint32_t sQ = base;
    const uint32_t sK = base + 8192;
    const uint32_t sV = base + 16384;

    const int tid = threadIdx.x, wid = tid >> 5, lid = tid & 31;
    const int b = blockIdx.z, h = blockIdx.y, q0 = blockIdx.x * 64;
    const int lane15 = lid & 15, lanehi = lid >> 4, xr = lane15 & 7;
    const int tig = lid & 3, gid = lid >> 2;
    const size_t RS = 3 * C_DIM;

    // ---- Q tile: 64 rows x 128B ----
#pragma unroll
    for (int i = 0; i < 4; i++) {
        int u = tid + i * 128;          // 0..511
        int r = u >> 3, cu = u & 7;
        const char* g = (const char*)(qkvh + (size_t)(b * SEQ + q0 + r) * RS + h * HD) + cu * 16;
        CPA16(sQ + (uint32_t)(r * 128 + ((cu ^ (r & 7)) * 16)), g);
    }
    asm volatile("cp.async.commit_group;");
    asm volatile("cp.async.wait_group 0;");
    __syncthreads();

    uint32_t qf[4][4];
    {
        const uint32_t qrb = (uint32_t)((wid * 16 + lane15) * 128);
#pragma unroll
        for (int ks = 0; ks < 4; ks++) {
            const uint32_t uoff = (uint32_t)(((ks * 2 + lanehi) ^ xr) * 16);
            ldsm4(qf[ks], sQ + qrb + uoff);
        }
    }

    // ---- past zero-token init ----
    const int tq0 = q0 + wid * 16 + gid, tq1 = tq0 + 8;
    const float* bk = bqkv_l + C_DIM + h * HD;
    const float* bv = bqkv_l + 2 * C_DIM + h * HD;
    float sp0 = 0.f, sp1 = 0.f;
    {
        const __half* q0p = qkvh + (size_t)(b * SEQ + tq0) * RS + h * HD + tig * 16;
        const __half* q1p = qkvh + (size_t)(b * SEQ + tq1) * RS + h * HD + tig * 16;
#pragma unroll
        for (int dd = 0; dd < 16; dd++) {
            float w = bk[tig * 16 + dd];
            sp0 += __half2float(q0p[dd]) * w;
            sp1 += __half2float(q1p[dd]) * w;
        }
        sp0 += __shfl_xor_sync(0xFFFFFFFF, sp0, 1); sp0 += __shfl_xor_sync(0xFFFFFFFF, sp0, 2);
        sp1 += __shfl_xor_sync(0xFFFFFFFF, sp1, 1); sp1 += __shfl_xor_sync(0xFFFFFFFF, sp1, 2);
    }
    const bool pv0 = (tq0 <= WIN - 1), pv1 = (tq1 <= WIN - 1);
    float m0 = pv0 ? sp0 : -1e30f, m1 = pv1 ? sp1 : -1e30f;
    float l0 = pv0 ? 1.f : 0.f,     l1 = pv1 ? 1.f : 0.f;
    float o[8][4];
#pragma unroll
    for (int nt = 0; nt < 8; nt++) {
        float bva = bv[nt * 8 + 2 * tig], bvb = bv[nt * 8 + 2 * tig + 1];
        o[nt][0] = pv0 ? bva : 0.f; o[nt][1] = pv0 ? bvb : 0.f;
        o[nt][2] = pv1 ? bva : 0.f; o[nt][3] = pv1 ? bvb : 0.f;
    }

    // ---- main loop over 64-key tiles ----
    const int jlo = (q0 > WIN) ? ((q0 - WIN) & ~63) : 0;
    for (int j0 = jlo; j0 < q0 + 64; j0 += 64) {
        __syncthreads();
#pragma unroll
        for (int i = 0; i < 8; i++) {
            int u = tid + i * 128;       // 0..1023
            int t = u >> 9, idx = u & 511;
            int r = idx >> 3, cu = idx & 7;
            const size_t coloff = (size_t)C_DIM * (1 + t) + h * HD;
            const char* g = (const char*)(qkvh + (size_t)(b * SEQ + j0 + r) * RS + coloff) + cu * 16;
            CPA16(sK + (uint32_t)(t * 8192 + r * 128 + ((cu ^ (r & 7)) * 16)), g);
        }
        asm volatile("cp.async.commit_group;");
        asm volatile("cp.async.wait_group 0;");
        __syncthreads();

        // S = Q.K^T
        float s[8][4];
#pragma unroll
        for (int nt = 0; nt < 8; nt++)
#pragma unroll
            for (int i = 0; i < 4; i++) s[nt][i] = 0.f;
#pragma unroll
        for (int ks = 0; ks < 4; ks++) {
            const uint32_t uoff = (uint32_t)(((ks * 2 + lanehi) ^ xr) * 16);
            uint32_t kf[4][4];
#pragma unroll
            for (int pt = 0; pt < 4; pt++)
                ldsm4(kf[pt], sK + (uint32_t)((pt * 16 + lane15) * 128) + uoff);
#pragma unroll
            for (int nt = 0; nt < 8; nt++) {
                const int pt = nt >> 1, oo = nt & 1;
                mma16816(s[nt], qf[ks], kf[pt][oo], kf[pt][oo + 2]);
            }
        }
        // mask
#pragma unroll
        for (int nt = 0; nt < 8; nt++)
#pragma unroll
            for (int i = 0; i < 4; i++) {
                int key = j0 + nt * 8 + 2 * tig + (i & 1);
                int tq = (i < 2) ? tq0 : tq1;
                int dlt = tq - key;
                if (dlt < 0 || dlt > WIN) s[nt][i] = -3.0e38f;
            }
        // online softmax
        float mc0 = -3.0e38f, mc1 = -3.0e38f;
#pragma unroll
        for (int nt = 0; nt < 8; nt++) {
            mc0 = fmaxf(mc0, fmaxf(s[nt][0], s[nt][1]));
            mc1 = fmaxf(mc1, fmaxf(s[nt][2], s[nt][3]));
        }
        mc0 = fmaxf(mc0, __shfl_xor_sync(0xFFFFFFFF, mc0, 1));
        mc0 = fmaxf(mc0, __shfl_xor_sync(0xFFFFFFFF, mc0, 2));
        mc1 = fmaxf(mc1, __shfl_xor_sync(0xFFFFFFFF, mc1, 1));
        mc1 = fmaxf(mc1, __shfl_xor_sync(0xFFFFFFFF, mc1, 2));
        float mn0 = fmaxf(m0, mc0), mn1 = fmaxf(m1, mc1);
        float a0 = __expf(m0 - mn0), a1 = __expf(m1 - mn1);
        float rs0 = 0.f, rs1 = 0.f;
#pragma unroll
        for (int nt = 0; nt < 8; nt++) {
            s[nt][0] = __expf(s[nt][0] - mn0); rs0 += s[nt][0];
            s[nt][1] = __expf(s[nt][1] - mn0); rs0 += s[nt][1];
            s[nt][2] = __expf(s[nt][2] - mn1); rs1 += s[nt][2];
            s[nt][3] = __expf(s[nt][3] - mn1); rs1 += s[nt][3];
        }
        rs0 += __shfl_xor_sync(0xFFFFFFFF, rs0, 1); rs0 += __shfl_xor_sync(0xFFFFFFFF, rs0, 2);
        rs1 += __shfl_xor_sync(0xFFFFFFFF, rs1, 1); rs1 += __shfl_xor_sync(0xFFFFFFFF, rs1, 2);
        l0 = l0 * a0 + rs0; l1 = l1 * a1 + rs1;
        m0 = mn0; m1 = mn1;
#pragma unroll
        for (int nt = 0; nt < 8; nt++) {
            o[nt][0] *= a0; o[nt][1] *= a0; o[nt][2] *= a1; o[nt][3] *= a1;
        }
        // pack P -> fp16 A-frags
        uint32_t pa[4][4];
#pragma unroll
        for (int kt = 0; kt < 4; kt++) {
            pa[kt][0] = packh(s[2 * kt][0],     s[2 * kt][1]);
            pa[kt][1] = packh(s[2 * kt][2],     s[2 * kt][3]);
            pa[kt][2] = packh(s[2 * kt + 1][0], s[2 * kt + 1][1]);
            pa[kt][3] = packh(s[2 * kt + 1][2], s[2 * kt + 1][3]);
        }
        // O += P * V
#pragma unroll
        for (int kt = 0; kt < 4; kt++) {
            const uint32_t vrb = (uint32_t)((kt * 16 + lane15) * 128);
            uint32_t vf[4][4];
#pragma unroll
            for (int j = 0; j < 4; j++) {
                const uint32_t uo = (uint32_t)(((j * 2 + lanehi) ^ xr) * 16);
                ldsm4t(vf[j], sV + vrb + uo);
            }
#pragma unroll
            for (int j = 0; j < 4; j++) {
                mma16816(o[2 * j],     pa[kt], vf[j][0], vf[j][1]);
                mma16816(o[2 * j + 1], pa[kt], vf[j][2], vf[j][3]);
            }
        }
    }

    const float r0 = 1.f / l0, r1 = 1.f / l1;
#pragma unroll
    for (int nt = 0; nt < 8; nt++) {
        const int col = h * HD + nt * 8 + 2 * tig;
        __half2 hh0 = __floats2half2_rn(o[nt][0] * r0, o[nt][1] * r0);
        __half2 hh1 = __floats2half2_rn(o[nt][2] * r1, o[nt][3] * r1);
        *(__half2*)(oh + (size_t)(b * SEQ + tq0) * C_DIM + col) = hh0;
        *(__half2*)(oh + (size_t)(b * SEQ + tq1) * C_DIM + col) = hh1;
    }
}

// ================= launcher =================
extern "C" void kernel_launch(void* const* d_in, const int* in_sizes, int n_in,
                              void* d_out, int out_size)
{
    const float* x      = (const float*)d_in[0];
    const float* norm_g = (const float*)d_in[1];
    const float* norm_b = (const float*)d_in[2];
    const float* Wqkv   = (const float*)d_in[3];
    const float* bqkv   = (const float*)d_in[4];
    const float* Wo     = (const float*)d_in[5];
    const float* bo     = (const float*)d_in[6];
    const float* ln1_g  = (const float*)d_in[7];
    const float* ln1_b  = (const float*)d_in[8];
    const float* ln2_g  = (const float*)d_in[9];
    const float* ln2_b  = (const float*)d_in[10];
    const float* W1     = (const float*)d_in[11];
    const float* b1     = (const float*)d_in[12];
    const float* W2     = (const float*)d_in[13];
    const float* b2     = (const float*)d_in[14];
    float* out = (float*)d_out;

    float *gx, *gtmp;
    __half *gxh, *gah, *ghh, *gwh, *gqh, *gvh;
    cudaGetSymbolAddress((void**)&gx,   g_x);
    cudaGetSymbolAddress((void**)&gtmp, g_tmp);
    cudaGetSymbolAddress((void**)&gxh,  g_xh);
    cudaGetSymbolAddress((void**)&gah,  g_ah);
    cudaGetSymbolAddress((void**)&ghh,  g_hh);
    cudaGetSymbolAddress((void**)&gwh,  g_wh);
    cudaGetSymbolAddress((void**)&gqh,  g_qkvh);
    cudaGetSymbolAddress((void**)&gvh,  g_vh);

    cudaFuncSetAttribute(gemm_hmma1<0>, cudaFuncAttributeMaxDynamicSharedMemorySize, GEMM_SMEM_BYTES);
    cudaFuncSetAttribute(gemm_hmma1<1>, cudaFuncAttributeMaxDynamicSharedMemorySize, GEMM_SMEM_BYTES);
    cudaFuncSetAttribute(gemm_hmma1<2>, cudaFuncAttributeMaxDynamicSharedMemorySize, GEMM_SMEM_BYTES);
    cudaFuncSetAttribute(attn_mma_kernel, cudaFuncAttributeMaxDynamicSharedMemorySize, ATTN_SMEM);

    const int CONV_BLK = 592;

    embed_ln_kernel<<<NROWS, 256>>>(x, norm_g, norm_b, gx, gxh);

    for (int l = 0; l < N_LAYERS; l++) {
        const size_t oQ = (size_t)l * 3 * C_DIM * C_DIM;
        const size_t oO = (size_t)l * C_DIM * C_DIM;
        const size_t o1 = (size_t)l * HID_DIM * C_DIM;
        const size_t o2 = (size_t)l * C_DIM * HID_DIM;
        const float* bqkv_l = bqkv + (size_t)l * 3 * C_DIM;

        // cast QKV weights, then Wo weights -> gemmQKV stays ncu launch #4
        cast_f16_kernel<<<CONV_BLK, 256>>>(Wqkv + oQ, gwh, 3 * C_DIM * C_DIM);
        cast_f16_kernel<<<CONV_BLK, 256>>>(Wo + oO, gvh, C_DIM * C_DIM);

        // qkv = (x @ Wqkv^T + bqkv), Q scaled by 1/8, fp16 out
        gemm_hmma1<2><<<dim3(3 * C_DIM / 128, NROWS / 128), 256, GEMM_SMEM_BYTES>>>(
            gxh, gwh, bqkv_l, nullptr, gqh,
            NROWS, 3 * C_DIM, C_DIM);

        // pure-fp16 HMMA flash attention
        attn_mma_kernel<<<dim3(SEQ / 64, N_HEADS, BATCH), 128, ATTN_SMEM>>>(
            gqh, bqkv_l, gah);

        // o = attn @ Wo^T + bo
        gemm_hmma1<0><<<dim3(C_DIM / 128, NROWS / 128), 256, GEMM_SMEM_BYTES>>>(
            gah, gvh, bo + (size_t)l * C_DIM, gtmp, nullptr,
            NROWS, C_DIM, C_DIM);

        // x = LN(x + o; ln1)
        add_ln_kernel<1><<<NROWS, 256>>>(gx, gtmp, ln1_g + l * C_DIM, ln1_b + l * C_DIM, gx, gxh);

        // hid = gelu(x @ W1^T + b1) -> fp16
        cast_f16_kernel<<<CONV_BLK, 256>>>(W1 + o1, gwh, HID_DIM * C_DIM);
        gemm_hmma1<1><<<dim3(HID_DIM / 128, NROWS / 128), 256, GEMM_SMEM_BYTES>>>(
            gxh, gwh, b1 + (size_t)l * HID_DIM, nullptr, ghh,
            NROWS, HID_DIM, C_DIM);

        // ff = hid @ W2^T + b2
        cast_f16_kernel<<<CONV_BLK, 256>>>(W2 + o2, gwh, C_DIM * HID_DIM);
        gemm_hmma1<0><<<dim3(C_DIM / 128, NROWS / 128), 256, GEMM_SMEM_BYTES>>>(
            ghh, gwh, b2 + (size_t)l * C_DIM, gtmp, nullptr,
            NROWS, C_DIM, HID_DIM);

        // x = LN(x + ff; ln2)
        if (l == N_LAYERS - 1)
            add_ln_kernel<0><<<NROWS, 256>>>(gx, gtmp, ln2_g + l * C_DIM, ln2_b + l * C_DIM, out, nullptr);
        else
            add_ln_kernel<1><<<NROWS, 256>>>(gx, gtmp, ln2_g + l * C_DIM, ln2_b + l * C_DIM, gx, gxh);
    }
}